// round 13
// baseline (speedup 1.0000x reference)
#include <cuda_runtime.h>
#include <cuda_fp16.h>
#include <cstdint>
#include <cstddef>

#define D_IN   788
#define D_HID  256
#define N_RELS 7
#define MAXN   50000
#define MAXE   800000
#define KP     832          // D_IN padded to 13*64
#define KT64   13           // K chunks of 64
#define MP     50176        // 392*128 padded rows
#define NMATS  8            // 7 relations + root

// ---------------- scratch (device globals; no allocations allowed) ----------------
__device__ __align__(16) __half g_Ah[(size_t)MP * KP];            // 83.5 MB
__device__ __align__(16) __half g_Bh[(size_t)NMATS * 256 * KP];   // 3.4 MB
__device__ __align__(16) __half g_xrelh[(size_t)N_RELS * MAXN * D_HID];  // 179 MB (fp16)
__device__ __align__(16) float g_out1[(size_t)MAXN * D_HID];             // 51 MB
__device__ __align__(16) float g_h2[(size_t)N_RELS * MAXN * 2];
__device__ float g_invcnt[(size_t)N_RELS * MAXN];
__device__ int   g_src[MAXE];
__device__ int   g_dst[MAXE];
__device__ int   g_et[MAXE];
__device__ int   g_deg[MAXN];
__device__ int   g_cursor[MAXN];
__device__ int   g_off[MAXN + 1];
__device__ int   g_csr[MAXE];        // src | (et<<20)
__device__ int   g_flags[2];

// ---------------- helpers ----------------
__device__ __forceinline__ uint32_t smem_u32(const void* p) {
    uint32_t a;
    asm("{ .reg .u64 t; cvta.to.shared.u64 t, %1; cvt.u32.u64 %0, t; }" : "=r"(a) : "l"(p));
    return a;
}
__device__ __forceinline__ void cpasync16(uint32_t saddr, const void* g) {
    asm volatile("cp.async.ca.shared.global [%0], [%1], 16;" :: "r"(saddr), "l"(g));
}
__device__ __forceinline__ void ldsm4(uint32_t* r, uint32_t addr) {
    asm volatile("ldmatrix.sync.aligned.m8n8.x4.shared.b16 {%0,%1,%2,%3}, [%4];"
                 : "=r"(r[0]), "=r"(r[1]), "=r"(r[2]), "=r"(r[3]) : "r"(addr));
}
__device__ __forceinline__ void mma16816(float* d, const uint32_t* a, uint32_t b0, uint32_t b1) {
    asm volatile("mma.sync.aligned.m16n8k16.row.col.f32.f16.f16.f32 "
                 "{%0,%1,%2,%3}, {%4,%5,%6,%7}, {%8,%9}, {%0,%1,%2,%3};"
                 : "+f"(d[0]), "+f"(d[1]), "+f"(d[2]), "+f"(d[3])
                 : "r"(a[0]), "r"(a[1]), "r"(a[2]), "r"(a[3]), "r"(b0), "r"(b1));
}

// ---------------- fp32 -> fp16 of X (vectorized, padded, zero-filled) ----------------
__global__ void __launch_bounds__(256) convert_x(const float* __restrict__ x,
                          __half* __restrict__ Ah, int N) {
    const int row = blockIdx.x;
    const int k = threadIdx.x * 4;
    if (k >= KP) return;
    float4 v = make_float4(0.f, 0.f, 0.f, 0.f);
    if (row < N && k < D_IN) v = *(const float4*)&x[(size_t)row * D_IN + k];
    __half2 h01 = make_half2(__float2half(v.x), __float2half(v.y));
    __half2 h23 = make_half2(__float2half(v.z), __float2half(v.w));
    const size_t o = (size_t)row * KP + k;
    *(__half2*)&Ah[o] = h01; *(__half2*)&Ah[o + 2] = h23;
}

// ---------------- transpose W1: Bt[mat*256+n][k] fp16 ----------------
__global__ void convert_w(const float* __restrict__ w1_rel, const float* __restrict__ w1_root,
                          __half* __restrict__ Bh) {
    const int r = blockIdx.y;            // 0..2047 -> mat = r>>8, n = r&255
    const int mat = r >> 8, n = r & 255;
    const int k = blockIdx.x * 256 + threadIdx.x;
    if (k >= KP) return;
    float v = 0.0f;
    if (k < D_IN) {
        if (mat < 7) v = w1_rel[((size_t)mat * D_IN + k) * 256 + n];
        else         v = w1_root[(size_t)k * 256 + n];
    }
    Bh[(size_t)r * KP + k] = __float2half(v);
}

// ---------------- dtype detection + index decode ----------------
__global__ void detect_kernel(const unsigned int* ei, const unsigned int* et, int E) {
    __shared__ int bad_ei, bad_et;
    if (threadIdx.x == 0) { bad_ei = 0; bad_et = 0; }
    __syncthreads();
    int n = E < 64 ? E : 64;
    if ((int)threadIdx.x < n) {
        if (ei[2 * threadIdx.x + 1] != 0u) bad_ei = 1;
        if (et[2 * threadIdx.x + 1] != 0u) bad_et = 1;
    }
    __syncthreads();
    if (threadIdx.x == 0) { g_flags[0] = !bad_ei; g_flags[1] = !bad_et; }
}

__global__ void decode_kernel(const void* ei, const void* et, int E) {
    int e = blockIdx.x * blockDim.x + threadIdx.x;
    if (e >= E) return;
    long long s, d, t;
    if (g_flags[0]) {
        const long long* p = (const long long*)ei;
        s = p[e]; d = p[(size_t)E + e];
    } else {
        const int* p = (const int*)ei;
        s = p[e]; d = p[(size_t)E + e];
    }
    if (g_flags[1]) t = ((const long long*)et)[e];
    else            t = ((const int*)et)[e];
    g_src[e] = (int)s; g_dst[e] = (int)d; g_et[e] = (int)t;
}

// ---------------- degree counting + CSR build ----------------
__global__ void zero_kernel(int NC, int N) {
    int i = blockIdx.x * blockDim.x + threadIdx.x;
    if (i < NC) g_invcnt[i] = 0.0f;
    if (i < N) { g_deg[i] = 0; g_cursor[i] = 0; }
}
__global__ void count_kernel(int E, int N) {
    int e = blockIdx.x * blockDim.x + threadIdx.x;
    if (e >= E) return;
    const int d = g_dst[e];
    atomicAdd(&g_invcnt[(size_t)g_et[e] * N + d], 1.0f);
    atomicAdd(&g_deg[d], 1);
}
__global__ void invcnt_kernel(int n) {
    int i = blockIdx.x * blockDim.x + threadIdx.x;
    if (i < n) g_invcnt[i] = 1.0f / fmaxf(g_invcnt[i], 1.0f);
}
// single-block exclusive scan of g_deg[0..N) -> g_off
__global__ void __launch_bounds__(1024) scan_kernel(int N) {
    __shared__ int ssum[1024];
    const int t = threadIdx.x;
    const int chunk = (N + 1023) / 1024;
    const int start = t * chunk;
    const int end = min(start + chunk, N);
    int s = 0;
    for (int i = start; i < end; i++) s += g_deg[i];
    ssum[t] = s;
    __syncthreads();
    for (int off = 1; off < 1024; off <<= 1) {
        int u = (t >= off) ? ssum[t - off] : 0;
        __syncthreads();
        ssum[t] += u;
        __syncthreads();
    }
    int run = ssum[t] - s;          // exclusive prefix of this chunk
    for (int i = start; i < end; i++) { g_off[i] = run; run += g_deg[i]; }
    if (t == 1023) g_off[N] = ssum[1023];
}
__global__ void fill_kernel(int E) {
    int e = blockIdx.x * blockDim.x + threadIdx.x;
    if (e >= E) return;
    const int d = g_dst[e];
    const int pos = atomicAdd(&g_cursor[d], 1);
    g_csr[g_off[d] + pos] = g_src[e] | (g_et[e] << 20);
}

// ---------------- HMMA GEMM slice: mats [mat0, mat0+gridDim.x) ----------------------
// CTA tile 128x256, BK=64, 16 warps (4Mx4N) of 32x64, 3-stage cp.async (wait_group 1),
// 1 barrier/iter. smem row stride 144B (128B data + 16B pad) -> conflict-free LDSM + STS.
#define ROWB     144
#define ARR_A    (128 * ROWB)      // 18432
#define ARR_B    (256 * ROWB)      // 36864
#define STG_A    0
#define STG_B    ARR_A
#define STAGE_SZ (ARR_A + ARR_B)   // 55296
#define NSTAGE   3
#define GEMM_SMEM (NSTAGE * STAGE_SZ)  // 165888

__global__ void __launch_bounds__(512, 1) hmma_gemm(
    const __half* __restrict__ Ah, const __half* __restrict__ Bh,
    const float* __restrict__ b1, __half* __restrict__ xrelh, float* __restrict__ out1,
    int N, int mat0)
{
    extern __shared__ char smem[];
    const uint32_t sbase = smem_u32(smem);
    const int mat = mat0 + blockIdx.x;
    const int m0 = blockIdx.y * 128;
    const int n0 = mat * 256;                        // B row offset for this matrix
    const int tid = threadIdx.x;
    const int warp = tid >> 5, lane = tid & 31;
    const int wm = (warp & 3) * 32, wn = (warp >> 2) * 64;

    float acc[2][8][4];
#pragma unroll
    for (int i = 0; i < 2; i++)
#pragma unroll
        for (int j = 0; j < 8; j++)
#pragma unroll
            for (int q = 0; q < 4; q++) acc[i][j][q] = 0.0f;

    const char* pAh = (const char*)Ah;
    const char* pBh = (const char*)Bh;

// chunk c = tid + 512*j: row = c>>3, h = c&7. A: j<2 (1024 chunks), B: j<4 (2048 chunks)
#define LOAD_TILE(kt, stage)                                                        \
    {                                                                               \
        const int k0b = (kt) * 128;                                                 \
        const uint32_t sst = sbase + (stage) * STAGE_SZ;                            \
        _Pragma("unroll")                                                           \
        for (int j = 0; j < 2; j++) {                                               \
            const int c = tid + 512 * j;                                            \
            const int row = c >> 3, h = c & 7;                                      \
            cpasync16(sst + STG_A + row * ROWB + h * 16,                            \
                      pAh + (size_t)(m0 + row) * (KP * 2) + k0b + h * 16);          \
        }                                                                           \
        _Pragma("unroll")                                                           \
        for (int j = 0; j < 4; j++) {                                               \
            const int c = tid + 512 * j;                                            \
            const int row = c >> 3, h = c & 7;                                      \
            cpasync16(sst + STG_B + row * ROWB + h * 16,                            \
                      pBh + (size_t)(n0 + row) * (KP * 2) + k0b + h * 16);          \
        }                                                                           \
        asm volatile("cp.async.commit_group;" ::: "memory");                        \
    }

    LOAD_TILE(0, 0);
    LOAD_TILE(1, 1);

    const int lmat = lane >> 3, lr = lane & 7;       // ldmatrix lane roles
    int stage = 0;
    for (int kt = 0; kt < KT64; kt++) {
        asm volatile("cp.async.wait_group 1;" ::: "memory");   // tile kt resident
        __syncthreads();                                       // + compute(kt-1) done
        if (kt + 2 < KT64) {
            const int ns = (stage + 2 >= NSTAGE) ? stage + 2 - NSTAGE : stage + 2;
            LOAD_TILE(kt + 2, ns);
        } else {
            asm volatile("cp.async.commit_group;" ::: "memory");  // keep group count
        }

        const uint32_t s = sbase + stage * STAGE_SZ;
#pragma unroll
        for (int kk = 0; kk < 4; kk++) {
            const int h = kk * 2 + (lmat >> 1);
            uint32_t ah[2][4], bh[4][4];
#pragma unroll
            for (int mt = 0; mt < 2; mt++) {
                const int row = wm + mt * 16 + (lmat & 1) * 8 + lr;
                ldsm4(ah[mt], s + STG_A + row * ROWB + h * 16);
            }
#pragma unroll
            for (int np = 0; np < 4; np++) {
                const int row = wn + np * 16 + (lmat & 1) * 8 + lr;
                ldsm4(bh[np], s + STG_B + row * ROWB + h * 16);
            }
#pragma unroll
            for (int mt = 0; mt < 2; mt++)
#pragma unroll
                for (int nt = 0; nt < 8; nt++) {
                    const int np = nt >> 1, sub = nt & 1;
                    mma16816(acc[mt][nt], ah[mt], bh[np][sub], bh[np][sub + 2]);
                }
        }
        stage = (stage + 1 >= NSTAGE) ? 0 : stage + 1;
    }

    // epilogue
    if (mat < 7) {
        __half* dsth = xrelh + (size_t)mat * N * 256;
#pragma unroll
        for (int mt = 0; mt < 2; mt++) {
#pragma unroll
            for (int nt = 0; nt < 8; nt++) {
                const int c = wn + nt * 8 + 2 * (lane & 3);
                const int r0 = m0 + wm + mt * 16 + (lane >> 2);
                if (r0 < N)
                    *(__half2*)&dsth[(size_t)r0 * 256 + c] =
                        __floats2half2_rn(acc[mt][nt][0], acc[mt][nt][1]);
                const int r1 = r0 + 8;
                if (r1 < N)
                    *(__half2*)&dsth[(size_t)r1 * 256 + c] =
                        __floats2half2_rn(acc[mt][nt][2], acc[mt][nt][3]);
            }
        }
    } else {
#pragma unroll
        for (int mt = 0; mt < 2; mt++) {
#pragma unroll
            for (int nt = 0; nt < 8; nt++) {
                const int c = wn + nt * 8 + 2 * (lane & 3);
                const float bb0 = b1[c], bb1 = b1[c + 1];
                const int r0 = m0 + wm + mt * 16 + (lane >> 2);
                if (r0 < N)
                    *(float2*)&out1[(size_t)r0 * 256 + c] =
                        make_float2(acc[mt][nt][0] + bb0, acc[mt][nt][1] + bb1);
                const int r1 = r0 + 8;
                if (r1 < N)
                    *(float2*)&out1[(size_t)r1 * 256 + c] =
                        make_float2(acc[mt][nt][2] + bb0, acc[mt][nt][3] + bb1);
            }
        }
    }
}

// ---------------- layer-1 aggregation (atomic-free): warp per dst node, rel window -------
__global__ void __launch_bounds__(256) gather1_kernel(int N, int tlo, int thi) {
    const int d    = (blockIdx.x * 256 + threadIdx.x) >> 5;
    const int lane = threadIdx.x & 31;
    if (d >= N) return;
    const int beg = g_off[d], end = g_off[d + 1];
    float acc[8];
#pragma unroll
    for (int i = 0; i < 8; i++) acc[i] = 0.0f;
    for (int j = beg; j < end; j++) {
        const int p = g_csr[j];
        const int t = p >> 20;
        if (t < tlo || t > thi) continue;
        const int s = p & 0xFFFFF;
        const float w = g_invcnt[(size_t)t * N + d];
        const uint4 v = ((const uint4*)&g_xrelh[((size_t)t * N + s) * D_HID])[lane];
        const __half2* hp = (const __half2*)&v;
        const float2 f0 = __half22float2(hp[0]), f1 = __half22float2(hp[1]);
        const float2 f2 = __half22float2(hp[2]), f3 = __half22float2(hp[3]);
        acc[0] += w * f0.x; acc[1] += w * f0.y; acc[2] += w * f1.x; acc[3] += w * f1.y;
        acc[4] += w * f2.x; acc[5] += w * f2.y; acc[6] += w * f3.x; acc[7] += w * f3.y;
    }
    float* dstp = &g_out1[(size_t)d * D_HID + lane * 8];
    float4 o0 = *(float4*)dstp, o1 = *(float4*)(dstp + 4);
    o0.x += acc[0]; o0.y += acc[1]; o0.z += acc[2]; o0.w += acc[3];
    o1.x += acc[4]; o1.y += acc[5]; o1.z += acc[6]; o1.w += acc[7];
    *(float4*)dstp = o0; *(float4*)(dstp + 4) = o1;
}

// ---------------- layer 2: h=relu(out1); 16 dots per node ----------------
__global__ void __launch_bounds__(256) layer2_kernel(
    const float* __restrict__ w2rel, const float* __restrict__ w2root,
    const float* __restrict__ b2, float* __restrict__ out, int N)
{
    __shared__ float ws[16][D_HID];
    const int tid = threadIdx.x;
    for (int idx = tid; idx < 16 * D_HID; idx += 256) {
        const int o = idx >> 8, k = idx & 255;
        float v;
        if (o < 14) v = w2rel[((size_t)(o >> 1) * D_HID + k) * 2 + (o & 1)];
        else        v = w2root[(size_t)k * 2 + (o & 1)];
        ws[o][k] = v;
    }
    __syncthreads();
    const int warp = tid >> 5, lane = tid & 31;
    const int n = blockIdx.x * 8 + warp;
    if (n >= N) return;
    float hv[8];
#pragma unroll
    for (int i = 0; i < 8; i++)
        hv[i] = fmaxf(g_out1[(size_t)n * D_HID + lane + 32 * i], 0.0f);
#pragma unroll
    for (int o = 0; o < 16; o++) {
        float sacc = 0.0f;
#pragma unroll
        for (int i = 0; i < 8; i++) sacc += hv[i] * ws[o][lane + 32 * i];
#pragma unroll
        for (int off = 16; off; off >>= 1) sacc += __shfl_xor_sync(0xffffffffu, sacc, off);
        if (lane == 0) {
            if (o < 14) g_h2[((size_t)(o >> 1) * N + n) * 2 + (o & 1)] = sacc;
            else        out[(size_t)n * 2 + (o & 1)] = sacc + b2[o & 1];
        }
    }
}

// ---------------- layer-2 edge scatter (tiny; atomics fine) ----------------
__global__ void scatter2_kernel(float* __restrict__ out, int E, int N) {
    const int e = blockIdx.x * blockDim.x + threadIdx.x;
    if (e >= E) return;
    const int s = g_src[e], d = g_dst[e], t = g_et[e];
    const float w = g_invcnt[(size_t)t * N + d];
    const float2 v = *(const float2*)&g_h2[((size_t)t * N + s) * 2];
    asm volatile("red.global.add.v2.f32 [%0], {%1, %2};"
                 :: "l"(out + (size_t)d * 2), "f"(v.x * w), "f"(v.y * w)
                 : "memory");
}

// ---------------- launch ----------------
extern "C" void kernel_launch(void* const* d_in, const int* in_sizes, int n_in,
                              void* d_out, int out_size) {
    const float* x       = (const float*)d_in[0];
    const void*  ei      = d_in[1];
    const void*  et      = d_in[2];
    const float* w1_rel  = (const float*)d_in[3];
    const float* w1_root = (const float*)d_in[4];
    const float* b1      = (const float*)d_in[5];
    const float* w2_rel  = (const float*)d_in[6];
    const float* w2_root = (const float*)d_in[7];
    const float* b2      = (const float*)d_in[8];
    float* out = (float*)d_out;

    const int N = in_sizes[0] / D_IN;
    const int E = in_sizes[2];

    static __half *Ah_p = nullptr, *Bh_p = nullptr, *xrelh_p = nullptr;
    static float *out1_p = nullptr;
    static cudaStream_t s2 = nullptr;
    static cudaEvent_t evFork = nullptr, evA = nullptr, evB = nullptr, evC = nullptr,
                       evDone = nullptr;
    if (!Ah_p) {
        cudaGetSymbolAddress((void**)&Ah_p, g_Ah);
        cudaGetSymbolAddress((void**)&Bh_p, g_Bh);
        cudaGetSymbolAddress((void**)&xrelh_p, g_xrelh);
        cudaGetSymbolAddress((void**)&out1_p, g_out1);
        cudaFuncSetAttribute(hmma_gemm, cudaFuncAttributeMaxDynamicSharedMemorySize, GEMM_SMEM);
        cudaStreamCreateWithFlags(&s2, cudaStreamNonBlocking);
        cudaEventCreateWithFlags(&evFork, cudaEventDisableTiming);
        cudaEventCreateWithFlags(&evA, cudaEventDisableTiming);
        cudaEventCreateWithFlags(&evB, cudaEventDisableTiming);
        cudaEventCreateWithFlags(&evC, cudaEventDisableTiming);
        cudaEventCreateWithFlags(&evDone, cudaEventDisableTiming);
    }

    // fork: CSR-build chain on s2, concurrent with converts + GEMM-A on the main stream
    cudaEventRecord(evFork, 0);
    cudaStreamWaitEvent(s2, evFork, 0);

    // s2: edge decoding + degree counts + CSR (independent of GEMM)
    detect_kernel<<<1, 128, 0, s2>>>((const unsigned int*)ei, (const unsigned int*)et, E);
    decode_kernel<<<(E + 255) / 256, 256, 0, s2>>>(ei, et, E);
    const int NC = N_RELS * N;
    zero_kernel<<<(NC + 255) / 256, 256, 0, s2>>>(NC, N);
    count_kernel<<<(E + 255) / 256, 256, 0, s2>>>(E, N);
    scan_kernel<<<1, 1024, 0, s2>>>(N);
    invcnt_kernel<<<(NC + 255) / 256, 256, 0, s2>>>(NC);
    fill_kernel<<<(E + 255) / 256, 256, 0, s2>>>(E);

    // main stream: conversions then GEMM-A (mats 4..7, includes root -> out1 ready)
    convert_x<<<MP, 256>>>(x, Ah_p, N);
    dim3 gw((KP + 255) / 256, NMATS * 256);
    convert_w<<<gw, 256>>>(w1_rel, w1_root, Bh_p);
    dim3 ggA(4, MP / 128);
    hmma_gemm<<<ggA, 512, GEMM_SMEM>>>(Ah_p, Bh_p, b1, xrelh_p, out1_p, N, 4);
    cudaEventRecord(evA, 0);

    // main stream: GEMM-B (mats 0..2) — concurrent with s2's gather of rels 4..6
    dim3 ggB(3, MP / 128);
    hmma_gemm<<<ggB, 512, GEMM_SMEM>>>(Ah_p, Bh_p, b1, xrelh_p, out1_p, N, 0);
    cudaEventRecord(evB, 0);

    // main stream: GEMM-C (mat 3) — concurrent with s2's gather of rels 0..2
    dim3 ggC(1, MP / 128);
    hmma_gemm<<<ggC, 512, GEMM_SMEM>>>(Ah_p, Bh_p, b1, xrelh_p, out1_p, N, 3);
    cudaEventRecord(evC, 0);

    // s2: staged gathers, each hiding under the next GEMM slice
    cudaStreamWaitEvent(s2, evA, 0);
    gather1_kernel<<<(N * 32 + 255) / 256, 256, 0, s2>>>(N, 4, 6);
    cudaStreamWaitEvent(s2, evB, 0);
    gather1_kernel<<<(N * 32 + 255) / 256, 256, 0, s2>>>(N, 0, 2);
    cudaStreamWaitEvent(s2, evC, 0);
    gather1_kernel<<<(N * 32 + 255) / 256, 256, 0, s2>>>(N, 3, 3);

    // s2: layer 2 + scatter (depend on completed out1 and CSR data)
    layer2_kernel<<<(N + 7) / 8, 256, 0, s2>>>(w2_rel, w2_root, b2, out, N);
    scatter2_kernel<<<(E + 255) / 256, 256, 0, s2>>>(out, E, N);

    // join back to the capture stream
    cudaEventRecord(evDone, s2);
    cudaStreamWaitEvent(0, evDone, 0);
}

// round 14
// speedup vs baseline: 1.0274x; 1.0274x over previous
#include <cuda_runtime.h>
#include <cuda_fp16.h>
#include <cstdint>
#include <cstddef>

#define D_IN   788
#define D_HID  256
#define N_RELS 7
#define MAXN   50000
#define MAXE   800000
#define KP     832          // D_IN padded to 13*64
#define KT64   13           // K chunks of 64
#define MP     50176        // 392*128 padded rows
#define NMATS  8            // 7 relations + root

// ---------------- scratch (device globals; no allocations allowed) ----------------
__device__ __align__(16) __half g_Ah[(size_t)MP * KP];            // 83.5 MB
__device__ __align__(16) __half g_Bh[(size_t)NMATS * 256 * KP];   // 3.4 MB
__device__ __align__(16) __half g_xrelh[(size_t)N_RELS * MAXN * D_HID];  // 179 MB (fp16)
__device__ __align__(16) float g_out1[(size_t)MAXN * D_HID];             // 51 MB
__device__ __align__(16) float g_h2[(size_t)N_RELS * MAXN * 2];
__device__ float g_invcnt[(size_t)N_RELS * MAXN];
__device__ int   g_src[MAXE];
__device__ int   g_dst[MAXE];
__device__ int   g_et[MAXE];
__device__ int   g_deg[MAXN];
__device__ int   g_cursor[MAXN];
__device__ int   g_off[MAXN + 1];
__device__ int   g_csr[MAXE];        // src | (et<<20)
__device__ int   g_flags[2];

// ---------------- helpers ----------------
__device__ __forceinline__ uint32_t smem_u32(const void* p) {
    uint32_t a;
    asm("{ .reg .u64 t; cvta.to.shared.u64 t, %1; cvt.u32.u64 %0, t; }" : "=r"(a) : "l"(p));
    return a;
}
__device__ __forceinline__ void cpasync16(uint32_t saddr, const void* g) {
    asm volatile("cp.async.ca.shared.global [%0], [%1], 16;" :: "r"(saddr), "l"(g));
}
__device__ __forceinline__ void ldsm4(uint32_t* r, uint32_t addr) {
    asm volatile("ldmatrix.sync.aligned.m8n8.x4.shared.b16 {%0,%1,%2,%3}, [%4];"
                 : "=r"(r[0]), "=r"(r[1]), "=r"(r[2]), "=r"(r[3]) : "r"(addr));
}
__device__ __forceinline__ void mma16816(float* d, const uint32_t* a, uint32_t b0, uint32_t b1) {
    asm volatile("mma.sync.aligned.m16n8k16.row.col.f32.f16.f16.f32 "
                 "{%0,%1,%2,%3}, {%4,%5,%6,%7}, {%8,%9}, {%0,%1,%2,%3};"
                 : "+f"(d[0]), "+f"(d[1]), "+f"(d[2]), "+f"(d[3])
                 : "r"(a[0]), "r"(a[1]), "r"(a[2]), "r"(a[3]), "r"(b0), "r"(b1));
}

// ---------------- fp32 -> fp16 of X (vectorized, padded, zero-filled) ----------------
__global__ void __launch_bounds__(256) convert_x(const float* __restrict__ x,
                          __half* __restrict__ Ah, int N) {
    const int row = blockIdx.x;
    const int k = threadIdx.x * 4;
    if (k >= KP) return;
    float4 v = make_float4(0.f, 0.f, 0.f, 0.f);
    if (row < N && k < D_IN) v = *(const float4*)&x[(size_t)row * D_IN + k];
    __half2 h01 = make_half2(__float2half(v.x), __float2half(v.y));
    __half2 h23 = make_half2(__float2half(v.z), __float2half(v.w));
    const size_t o = (size_t)row * KP + k;
    *(__half2*)&Ah[o] = h01; *(__half2*)&Ah[o + 2] = h23;
}

// ---------------- transpose W1: Bt[mat*256+n][k] fp16 ----------------
__global__ void convert_w(const float* __restrict__ w1_rel, const float* __restrict__ w1_root,
                          __half* __restrict__ Bh) {
    const int r = blockIdx.y;            // 0..2047 -> mat = r>>8, n = r&255
    const int mat = r >> 8, n = r & 255;
    const int k = blockIdx.x * 256 + threadIdx.x;
    if (k >= KP) return;
    float v = 0.0f;
    if (k < D_IN) {
        if (mat < 7) v = w1_rel[((size_t)mat * D_IN + k) * 256 + n];
        else         v = w1_root[(size_t)k * 256 + n];
    }
    Bh[(size_t)r * KP + k] = __float2half(v);
}

// ---------------- dtype detection + index decode ----------------
__global__ void detect_kernel(const unsigned int* ei, const unsigned int* et, int E) {
    __shared__ int bad_ei, bad_et;
    if (threadIdx.x == 0) { bad_ei = 0; bad_et = 0; }
    __syncthreads();
    int n = E < 64 ? E : 64;
    if ((int)threadIdx.x < n) {
        if (ei[2 * threadIdx.x + 1] != 0u) bad_ei = 1;
        if (et[2 * threadIdx.x + 1] != 0u) bad_et = 1;
    }
    __syncthreads();
    if (threadIdx.x == 0) { g_flags[0] = !bad_ei; g_flags[1] = !bad_et; }
}

__global__ void decode_kernel(const void* ei, const void* et, int E) {
    int e = blockIdx.x * blockDim.x + threadIdx.x;
    if (e >= E) return;
    long long s, d, t;
    if (g_flags[0]) {
        const long long* p = (const long long*)ei;
        s = p[e]; d = p[(size_t)E + e];
    } else {
        const int* p = (const int*)ei;
        s = p[e]; d = p[(size_t)E + e];
    }
    if (g_flags[1]) t = ((const long long*)et)[e];
    else            t = ((const int*)et)[e];
    g_src[e] = (int)s; g_dst[e] = (int)d; g_et[e] = (int)t;
}

// ---------------- degree counting + CSR build ----------------
__global__ void zero_kernel(int NC, int N) {
    int i = blockIdx.x * blockDim.x + threadIdx.x;
    if (i < NC) g_invcnt[i] = 0.0f;
    if (i < N) { g_deg[i] = 0; g_cursor[i] = 0; }
}
__global__ void count_kernel(int E, int N) {
    int e = blockIdx.x * blockDim.x + threadIdx.x;
    if (e >= E) return;
    const int d = g_dst[e];
    atomicAdd(&g_invcnt[(size_t)g_et[e] * N + d], 1.0f);
    atomicAdd(&g_deg[d], 1);
}
__global__ void invcnt_kernel(int n) {
    int i = blockIdx.x * blockDim.x + threadIdx.x;
    if (i < n) g_invcnt[i] = 1.0f / fmaxf(g_invcnt[i], 1.0f);
}
// single-block exclusive scan of g_deg[0..N) -> g_off
__global__ void __launch_bounds__(1024) scan_kernel(int N) {
    __shared__ int ssum[1024];
    const int t = threadIdx.x;
    const int chunk = (N + 1023) / 1024;
    const int start = t * chunk;
    const int end = min(start + chunk, N);
    int s = 0;
    for (int i = start; i < end; i++) s += g_deg[i];
    ssum[t] = s;
    __syncthreads();
    for (int off = 1; off < 1024; off <<= 1) {
        int u = (t >= off) ? ssum[t - off] : 0;
        __syncthreads();
        ssum[t] += u;
        __syncthreads();
    }
    int run = ssum[t] - s;          // exclusive prefix of this chunk
    for (int i = start; i < end; i++) { g_off[i] = run; run += g_deg[i]; }
    if (t == 1023) g_off[N] = ssum[1023];
}
__global__ void fill_kernel(int E) {
    int e = blockIdx.x * blockDim.x + threadIdx.x;
    if (e >= E) return;
    const int d = g_dst[e];
    const int pos = atomicAdd(&g_cursor[d], 1);
    g_csr[g_off[d] + pos] = g_src[e] | (g_et[e] << 20);
}

// ---------------- HMMA GEMM slice: mats [mat0, mat0+gridDim.x) ----------------------
// CTA tile 128x256, BK=64, 16 warps (4Mx4N) of 32x64, 3-stage cp.async (wait_group 1),
// 1 barrier/iter. smem row stride 144B (128B data + 16B pad) -> conflict-free LDSM + STS.
#define ROWB     144
#define ARR_A    (128 * ROWB)      // 18432
#define ARR_B    (256 * ROWB)      // 36864
#define STG_A    0
#define STG_B    ARR_A
#define STAGE_SZ (ARR_A + ARR_B)   // 55296
#define NSTAGE   3
#define GEMM_SMEM (NSTAGE * STAGE_SZ)  // 165888

__global__ void __launch_bounds__(512, 1) hmma_gemm(
    const __half* __restrict__ Ah, const __half* __restrict__ Bh,
    const float* __restrict__ b1, __half* __restrict__ xrelh, float* __restrict__ out1,
    int N, int mat0)
{
    extern __shared__ char smem[];
    const uint32_t sbase = smem_u32(smem);
    const int mat = mat0 + blockIdx.x;
    const int m0 = blockIdx.y * 128;
    const int n0 = mat * 256;                        // B row offset for this matrix
    const int tid = threadIdx.x;
    const int warp = tid >> 5, lane = tid & 31;
    const int wm = (warp & 3) * 32, wn = (warp >> 2) * 64;

    float acc[2][8][4];
#pragma unroll
    for (int i = 0; i < 2; i++)
#pragma unroll
        for (int j = 0; j < 8; j++)
#pragma unroll
            for (int q = 0; q < 4; q++) acc[i][j][q] = 0.0f;

    const char* pAh = (const char*)Ah;
    const char* pBh = (const char*)Bh;

// chunk c = tid + 512*j: row = c>>3, h = c&7. A: j<2 (1024 chunks), B: j<4 (2048 chunks)
#define LOAD_TILE(kt, stage)                                                        \
    {                                                                               \
        const int k0b = (kt) * 128;                                                 \
        const uint32_t sst = sbase + (stage) * STAGE_SZ;                            \
        _Pragma("unroll")                                                           \
        for (int j = 0; j < 2; j++) {                                               \
            const int c = tid + 512 * j;                                            \
            const int row = c >> 3, h = c & 7;                                      \
            cpasync16(sst + STG_A + row * ROWB + h * 16,                            \
                      pAh + (size_t)(m0 + row) * (KP * 2) + k0b + h * 16);          \
        }                                                                           \
        _Pragma("unroll")                                                           \
        for (int j = 0; j < 4; j++) {                                               \
            const int c = tid + 512 * j;                                            \
            const int row = c >> 3, h = c & 7;                                      \
            cpasync16(sst + STG_B + row * ROWB + h * 16,                            \
                      pBh + (size_t)(n0 + row) * (KP * 2) + k0b + h * 16);          \
        }                                                                           \
        asm volatile("cp.async.commit_group;" ::: "memory");                        \
    }

    LOAD_TILE(0, 0);
    LOAD_TILE(1, 1);

    const int lmat = lane >> 3, lr = lane & 7;       // ldmatrix lane roles
    int stage = 0;
    for (int kt = 0; kt < KT64; kt++) {
        asm volatile("cp.async.wait_group 1;" ::: "memory");   // tile kt resident
        __syncthreads();                                       // + compute(kt-1) done
        if (kt + 2 < KT64) {
            const int ns = (stage + 2 >= NSTAGE) ? stage + 2 - NSTAGE : stage + 2;
            LOAD_TILE(kt + 2, ns);
        } else {
            asm volatile("cp.async.commit_group;" ::: "memory");  // keep group count
        }

        const uint32_t s = sbase + stage * STAGE_SZ;
#pragma unroll
        for (int kk = 0; kk < 4; kk++) {
            const int h = kk * 2 + (lmat >> 1);
            uint32_t ah[2][4], bh[4][4];
#pragma unroll
            for (int mt = 0; mt < 2; mt++) {
                const int row = wm + mt * 16 + (lmat & 1) * 8 + lr;
                ldsm4(ah[mt], s + STG_A + row * ROWB + h * 16);
            }
#pragma unroll
            for (int np = 0; np < 4; np++) {
                const int row = wn + np * 16 + (lmat & 1) * 8 + lr;
                ldsm4(bh[np], s + STG_B + row * ROWB + h * 16);
            }
#pragma unroll
            for (int mt = 0; mt < 2; mt++)
#pragma unroll
                for (int nt = 0; nt < 8; nt++) {
                    const int np = nt >> 1, sub = nt & 1;
                    mma16816(acc[mt][nt], ah[mt], bh[np][sub], bh[np][sub + 2]);
                }
        }
        stage = (stage + 1 >= NSTAGE) ? 0 : stage + 1;
    }

    // epilogue
    if (mat < 7) {
        __half* dsth = xrelh + (size_t)mat * N * 256;
#pragma unroll
        for (int mt = 0; mt < 2; mt++) {
#pragma unroll
            for (int nt = 0; nt < 8; nt++) {
                const int c = wn + nt * 8 + 2 * (lane & 3);
                const int r0 = m0 + wm + mt * 16 + (lane >> 2);
                if (r0 < N)
                    *(__half2*)&dsth[(size_t)r0 * 256 + c] =
                        __floats2half2_rn(acc[mt][nt][0], acc[mt][nt][1]);
                const int r1 = r0 + 8;
                if (r1 < N)
                    *(__half2*)&dsth[(size_t)r1 * 256 + c] =
                        __floats2half2_rn(acc[mt][nt][2], acc[mt][nt][3]);
            }
        }
    } else {
#pragma unroll
        for (int mt = 0; mt < 2; mt++) {
#pragma unroll
            for (int nt = 0; nt < 8; nt++) {
                const int c = wn + nt * 8 + 2 * (lane & 3);
                const float bb0 = b1[c], bb1 = b1[c + 1];
                const int r0 = m0 + wm + mt * 16 + (lane >> 2);
                if (r0 < N)
                    *(float2*)&out1[(size_t)r0 * 256 + c] =
                        make_float2(acc[mt][nt][0] + bb0, acc[mt][nt][1] + bb1);
                const int r1 = r0 + 8;
                if (r1 < N)
                    *(float2*)&out1[(size_t)r1 * 256 + c] =
                        make_float2(acc[mt][nt][2] + bb0, acc[mt][nt][3] + bb1);
            }
        }
    }
}

// ---------------- layer-1 aggregation (atomic-free): warp per dst node, rel window -------
__global__ void __launch_bounds__(256) gather1_kernel(int N, int tlo, int thi) {
    const int d    = (blockIdx.x * 256 + threadIdx.x) >> 5;
    const int lane = threadIdx.x & 31;
    if (d >= N) return;
    const int beg = g_off[d], end = g_off[d + 1];
    float acc[8];
#pragma unroll
    for (int i = 0; i < 8; i++) acc[i] = 0.0f;
    for (int j = beg; j < end; j++) {
        const int p = g_csr[j];
        const int t = p >> 20;
        if (t < tlo || t > thi) continue;
        const int s = p & 0xFFFFF;
        const float w = g_invcnt[(size_t)t * N + d];
        const uint4 v = ((const uint4*)&g_xrelh[((size_t)t * N + s) * D_HID])[lane];
        const __half2* hp = (const __half2*)&v;
        const float2 f0 = __half22float2(hp[0]), f1 = __half22float2(hp[1]);
        const float2 f2 = __half22float2(hp[2]), f3 = __half22float2(hp[3]);
        acc[0] += w * f0.x; acc[1] += w * f0.y; acc[2] += w * f1.x; acc[3] += w * f1.y;
        acc[4] += w * f2.x; acc[5] += w * f2.y; acc[6] += w * f3.x; acc[7] += w * f3.y;
    }
    float* dstp = &g_out1[(size_t)d * D_HID + lane * 8];
    float4 o0 = *(float4*)dstp, o1 = *(float4*)(dstp + 4);
    o0.x += acc[0]; o0.y += acc[1]; o0.z += acc[2]; o0.w += acc[3];
    o1.x += acc[4]; o1.y += acc[5]; o1.z += acc[6]; o1.w += acc[7];
    *(float4*)dstp = o0; *(float4*)(dstp + 4) = o1;
}

// ---------------- layer 2: h=relu(out1); 16 dots per node ----------------
__global__ void __launch_bounds__(256) layer2_kernel(
    const float* __restrict__ w2rel, const float* __restrict__ w2root,
    const float* __restrict__ b2, float* __restrict__ out, int N)
{
    __shared__ float ws[16][D_HID];
    const int tid = threadIdx.x;
    for (int idx = tid; idx < 16 * D_HID; idx += 256) {
        const int o = idx >> 8, k = idx & 255;
        float v;
        if (o < 14) v = w2rel[((size_t)(o >> 1) * D_HID + k) * 2 + (o & 1)];
        else        v = w2root[(size_t)k * 2 + (o & 1)];
        ws[o][k] = v;
    }
    __syncthreads();
    const int warp = tid >> 5, lane = tid & 31;
    const int n = blockIdx.x * 8 + warp;
    if (n >= N) return;
    float hv[8];
#pragma unroll
    for (int i = 0; i < 8; i++)
        hv[i] = fmaxf(g_out1[(size_t)n * D_HID + lane + 32 * i], 0.0f);
#pragma unroll
    for (int o = 0; o < 16; o++) {
        float sacc = 0.0f;
#pragma unroll
        for (int i = 0; i < 8; i++) sacc += hv[i] * ws[o][lane + 32 * i];
#pragma unroll
        for (int off = 16; off; off >>= 1) sacc += __shfl_xor_sync(0xffffffffu, sacc, off);
        if (lane == 0) {
            if (o < 14) g_h2[((size_t)(o >> 1) * N + n) * 2 + (o & 1)] = sacc;
            else        out[(size_t)n * 2 + (o & 1)] = sacc + b2[o & 1];
        }
    }
}

// ---------------- layer-2 edge scatter (tiny; atomics fine) ----------------
__global__ void scatter2_kernel(float* __restrict__ out, int E, int N) {
    const int e = blockIdx.x * blockDim.x + threadIdx.x;
    if (e >= E) return;
    const int s = g_src[e], d = g_dst[e], t = g_et[e];
    const float w = g_invcnt[(size_t)t * N + d];
    const float2 v = *(const float2*)&g_h2[((size_t)t * N + s) * 2];
    asm volatile("red.global.add.v2.f32 [%0], {%1, %2};"
                 :: "l"(out + (size_t)d * 2), "f"(v.x * w), "f"(v.y * w)
                 : "memory");
}

// ---------------- launch ----------------
extern "C" void kernel_launch(void* const* d_in, const int* in_sizes, int n_in,
                              void* d_out, int out_size) {
    const float* x       = (const float*)d_in[0];
    const void*  ei      = d_in[1];
    const void*  et      = d_in[2];
    const float* w1_rel  = (const float*)d_in[3];
    const float* w1_root = (const float*)d_in[4];
    const float* b1      = (const float*)d_in[5];
    const float* w2_rel  = (const float*)d_in[6];
    const float* w2_root = (const float*)d_in[7];
    const float* b2      = (const float*)d_in[8];
    float* out = (float*)d_out;

    const int N = in_sizes[0] / D_IN;
    const int E = in_sizes[2];

    static __half *Ah_p = nullptr, *Bh_p = nullptr, *xrelh_p = nullptr;
    static float *out1_p = nullptr;
    static cudaStream_t s2 = nullptr;
    static cudaEvent_t evFork = nullptr, evA = nullptr, evB = nullptr, evDone = nullptr;
    if (!Ah_p) {
        cudaGetSymbolAddress((void**)&Ah_p, g_Ah);
        cudaGetSymbolAddress((void**)&Bh_p, g_Bh);
        cudaGetSymbolAddress((void**)&xrelh_p, g_xrelh);
        cudaGetSymbolAddress((void**)&out1_p, g_out1);
        cudaFuncSetAttribute(hmma_gemm, cudaFuncAttributeMaxDynamicSharedMemorySize, GEMM_SMEM);
        cudaStreamCreateWithFlags(&s2, cudaStreamNonBlocking);
        cudaEventCreateWithFlags(&evFork, cudaEventDisableTiming);
        cudaEventCreateWithFlags(&evA, cudaEventDisableTiming);
        cudaEventCreateWithFlags(&evB, cudaEventDisableTiming);
        cudaEventCreateWithFlags(&evDone, cudaEventDisableTiming);
    }

    // fork: CSR-build chain on s2, concurrent with converts + GEMM-A on the main stream
    cudaEventRecord(evFork, 0);
    cudaStreamWaitEvent(s2, evFork, 0);

    // s2: edge decoding + degree counts + CSR (independent of GEMM)
    detect_kernel<<<1, 128, 0, s2>>>((const unsigned int*)ei, (const unsigned int*)et, E);
    decode_kernel<<<(E + 255) / 256, 256, 0, s2>>>(ei, et, E);
    const int NC = N_RELS * N;
    zero_kernel<<<(NC + 255) / 256, 256, 0, s2>>>(NC, N);
    count_kernel<<<(E + 255) / 256, 256, 0, s2>>>(E, N);
    scan_kernel<<<1, 1024, 0, s2>>>(N);
    invcnt_kernel<<<(NC + 255) / 256, 256, 0, s2>>>(NC);
    fill_kernel<<<(E + 255) / 256, 256, 0, s2>>>(E);

    // main stream: conversions then GEMM-A (mats 2..7, includes root -> out1 ready)
    convert_x<<<MP, 256>>>(x, Ah_p, N);
    dim3 gw((KP + 255) / 256, NMATS * 256);
    convert_w<<<gw, 256>>>(w1_rel, w1_root, Bh_p);
    dim3 ggA(6, MP / 128);
    hmma_gemm<<<ggA, 512, GEMM_SMEM>>>(Ah_p, Bh_p, b1, xrelh_p, out1_p, N, 2);
    cudaEventRecord(evA, 0);

    // main stream: GEMM-B (mats 0..1) — concurrent with s2's gather of rels 2..6
    dim3 ggB(2, MP / 128);
    hmma_gemm<<<ggB, 512, GEMM_SMEM>>>(Ah_p, Bh_p, b1, xrelh_p, out1_p, N, 0);
    cudaEventRecord(evB, 0);

    // s2: gather rels 2..6 under GEMM-B, then the small exposed tail (rels 0..1)
    cudaStreamWaitEvent(s2, evA, 0);
    gather1_kernel<<<(N * 32 + 255) / 256, 256, 0, s2>>>(N, 2, 6);
    cudaStreamWaitEvent(s2, evB, 0);
    gather1_kernel<<<(N * 32 + 255) / 256, 256, 0, s2>>>(N, 0, 1);

    // s2: layer 2 + scatter (depend on completed out1 and CSR data)
    layer2_kernel<<<(N + 7) / 8, 256, 0, s2>>>(w2_rel, w2_root, b2, out, N);
    scatter2_kernel<<<(E + 255) / 256, 256, 0, s2>>>(out, E, N);

    // join back to the capture stream
    cudaEventRecord(evDone, s2);
    cudaStreamWaitEvent(0, evDone, 0);
}

// round 15
// speedup vs baseline: 1.0415x; 1.0138x over previous
#include <cuda_runtime.h>
#include <cuda_fp16.h>
#include <cstdint>
#include <cstddef>

#define D_IN   788
#define D_HID  256
#define N_RELS 7
#define MAXN   50000
#define MAXE   800000
#define KP     832          // D_IN padded to 13*64
#define KT64   13           // K chunks of 64
#define MP     50176        // 392*128 padded rows
#define MTILES 392
#define NMATS  8            // 7 relations + root

// ---------------- scratch (device globals; no allocations allowed) ----------------
__device__ __align__(16) __half g_Ah[(size_t)MP * KP];            // 83.5 MB
__device__ __align__(16) __half g_Bh[(size_t)NMATS * 256 * KP];   // 3.4 MB
__device__ __align__(16) __half g_xrelh[(size_t)N_RELS * MAXN * D_HID];  // 179 MB (fp16)
__device__ __align__(16) float g_out1[(size_t)MAXN * D_HID];             // 51 MB
__device__ __align__(16) float g_h2[(size_t)N_RELS * MAXN * 2];
__device__ float g_invcnt[(size_t)N_RELS * MAXN];
__device__ int   g_src[MAXE];
__device__ int   g_dst[MAXE];
__device__ int   g_et[MAXE];
__device__ int   g_deg[MAXN];
__device__ int   g_cursor[MAXN];
__device__ int   g_off[MAXN + 1];
__device__ int   g_csr[MAXE];        // src | (et<<20)
__device__ int   g_flags[2];

// ---------------- helpers ----------------
__device__ __forceinline__ uint32_t smem_u32(const void* p) {
    uint32_t a;
    asm("{ .reg .u64 t; cvta.to.shared.u64 t, %1; cvt.u32.u64 %0, t; }" : "=r"(a) : "l"(p));
    return a;
}
__device__ __forceinline__ void cpasync16(uint32_t saddr, const void* g) {
    asm volatile("cp.async.ca.shared.global [%0], [%1], 16;" :: "r"(saddr), "l"(g));
}
__device__ __forceinline__ void ldsm4(uint32_t* r, uint32_t addr) {
    asm volatile("ldmatrix.sync.aligned.m8n8.x4.shared.b16 {%0,%1,%2,%3}, [%4];"
                 : "=r"(r[0]), "=r"(r[1]), "=r"(r[2]), "=r"(r[3]) : "r"(addr));
}
__device__ __forceinline__ void mma16816(float* d, const uint32_t* a, uint32_t b0, uint32_t b1) {
    asm volatile("mma.sync.aligned.m16n8k16.row.col.f32.f16.f16.f32 "
                 "{%0,%1,%2,%3}, {%4,%5,%6,%7}, {%8,%9}, {%0,%1,%2,%3};"
                 : "+f"(d[0]), "+f"(d[1]), "+f"(d[2]), "+f"(d[3])
                 : "r"(a[0]), "r"(a[1]), "r"(a[2]), "r"(a[3]), "r"(b0), "r"(b1));
}

// ---------------- fp32 -> fp16 of X rows [rowbase, rowbase+gridDim.x) ----------------
__global__ void __launch_bounds__(256) convert_x(const float* __restrict__ x,
                          __half* __restrict__ Ah, int N, int rowbase) {
    const int row = rowbase + blockIdx.x;
    const int k = threadIdx.x * 4;
    if (k >= KP) return;
    float4 v = make_float4(0.f, 0.f, 0.f, 0.f);
    if (row < N && k < D_IN) v = *(const float4*)&x[(size_t)row * D_IN + k];
    __half2 h01 = make_half2(__float2half(v.x), __float2half(v.y));
    __half2 h23 = make_half2(__float2half(v.z), __float2half(v.w));
    const size_t o = (size_t)row * KP + k;
    *(__half2*)&Ah[o] = h01; *(__half2*)&Ah[o + 2] = h23;
}

// ---------------- transpose W1: Bt[mat*256+n][k] fp16 ----------------
__global__ void convert_w(const float* __restrict__ w1_rel, const float* __restrict__ w1_root,
                          __half* __restrict__ Bh) {
    const int r = blockIdx.y;            // 0..2047 -> mat = r>>8, n = r&255
    const int mat = r >> 8, n = r & 255;
    const int k = blockIdx.x * 256 + threadIdx.x;
    if (k >= KP) return;
    float v = 0.0f;
    if (k < D_IN) {
        if (mat < 7) v = w1_rel[((size_t)mat * D_IN + k) * 256 + n];
        else         v = w1_root[(size_t)k * 256 + n];
    }
    Bh[(size_t)r * KP + k] = __float2half(v);
}

// ---------------- dtype detection + index decode ----------------
__global__ void detect_kernel(const unsigned int* ei, const unsigned int* et, int E) {
    __shared__ int bad_ei, bad_et;
    if (threadIdx.x == 0) { bad_ei = 0; bad_et = 0; }
    __syncthreads();
    int n = E < 64 ? E : 64;
    if ((int)threadIdx.x < n) {
        if (ei[2 * threadIdx.x + 1] != 0u) bad_ei = 1;
        if (et[2 * threadIdx.x + 1] != 0u) bad_et = 1;
    }
    __syncthreads();
    if (threadIdx.x == 0) { g_flags[0] = !bad_ei; g_flags[1] = !bad_et; }
}

__global__ void decode_kernel(const void* ei, const void* et, int E) {
    int e = blockIdx.x * blockDim.x + threadIdx.x;
    if (e >= E) return;
    long long s, d, t;
    if (g_flags[0]) {
        const long long* p = (const long long*)ei;
        s = p[e]; d = p[(size_t)E + e];
    } else {
        const int* p = (const int*)ei;
        s = p[e]; d = p[(size_t)E + e];
    }
    if (g_flags[1]) t = ((const long long*)et)[e];
    else            t = ((const int*)et)[e];
    g_src[e] = (int)s; g_dst[e] = (int)d; g_et[e] = (int)t;
}

// ---------------- degree counting + CSR build ----------------
__global__ void zero_kernel(int NC, int N) {
    int i = blockIdx.x * blockDim.x + threadIdx.x;
    if (i < NC) g_invcnt[i] = 0.0f;
    if (i < N) { g_deg[i] = 0; g_cursor[i] = 0; }
}
__global__ void count_kernel(int E, int N) {
    int e = blockIdx.x * blockDim.x + threadIdx.x;
    if (e >= E) return;
    const int d = g_dst[e];
    atomicAdd(&g_invcnt[(size_t)g_et[e] * N + d], 1.0f);
    atomicAdd(&g_deg[d], 1);
}
__global__ void invcnt_kernel(int n) {
    int i = blockIdx.x * blockDim.x + threadIdx.x;
    if (i < n) g_invcnt[i] = 1.0f / fmaxf(g_invcnt[i], 1.0f);
}
// single-block exclusive scan of g_deg[0..N) -> g_off
__global__ void __launch_bounds__(1024) scan_kernel(int N) {
    __shared__ int ssum[1024];
    const int t = threadIdx.x;
    const int chunk = (N + 1023) / 1024;
    const int start = t * chunk;
    const int end = min(start + chunk, N);
    int s = 0;
    for (int i = start; i < end; i++) s += g_deg[i];
    ssum[t] = s;
    __syncthreads();
    for (int off = 1; off < 1024; off <<= 1) {
        int u = (t >= off) ? ssum[t - off] : 0;
        __syncthreads();
        ssum[t] += u;
        __syncthreads();
    }
    int run = ssum[t] - s;          // exclusive prefix of this chunk
    for (int i = start; i < end; i++) { g_off[i] = run; run += g_deg[i]; }
    if (t == 1023) g_off[N] = ssum[1023];
}
__global__ void fill_kernel(int E) {
    int e = blockIdx.x * blockDim.x + threadIdx.x;
    if (e >= E) return;
    const int d = g_dst[e];
    const int pos = atomicAdd(&g_cursor[d], 1);
    g_csr[g_off[d] + pos] = g_src[e] | (g_et[e] << 20);
}

// ---------------- HMMA GEMM slice: mats [mat0, ...), row tiles [row0, ...) --------------
// CTA tile 128x256, BK=64, 16 warps (4Mx4N) of 32x64, 3-stage cp.async (wait_group 1),
// 1 barrier/iter. smem row stride 144B (128B data + 16B pad) -> conflict-free LDSM + STS.
#define ROWB     144
#define ARR_A    (128 * ROWB)      // 18432
#define ARR_B    (256 * ROWB)      // 36864
#define STG_A    0
#define STG_B    ARR_A
#define STAGE_SZ (ARR_A + ARR_B)   // 55296
#define NSTAGE   3
#define GEMM_SMEM (NSTAGE * STAGE_SZ)  // 165888

__global__ void __launch_bounds__(512, 1) hmma_gemm(
    const __half* __restrict__ Ah, const __half* __restrict__ Bh,
    const float* __restrict__ b1, __half* __restrict__ xrelh, float* __restrict__ out1,
    int N, int mat0, int row0)
{
    extern __shared__ char smem[];
    const uint32_t sbase = smem_u32(smem);
    const int mat = mat0 + blockIdx.x;
    const int m0 = (row0 + blockIdx.y) * 128;
    const int n0 = mat * 256;                        // B row offset for this matrix
    const int tid = threadIdx.x;
    const int warp = tid >> 5, lane = tid & 31;
    const int wm = (warp & 3) * 32, wn = (warp >> 2) * 64;

    float acc[2][8][4];
#pragma unroll
    for (int i = 0; i < 2; i++)
#pragma unroll
        for (int j = 0; j < 8; j++)
#pragma unroll
            for (int q = 0; q < 4; q++) acc[i][j][q] = 0.0f;

    const char* pAh = (const char*)Ah;
    const char* pBh = (const char*)Bh;

// chunk c = tid + 512*j: row = c>>3, h = c&7. A: j<2 (1024 chunks), B: j<4 (2048 chunks)
#define LOAD_TILE(kt, stage)                                                        \
    {                                                                               \
        const int k0b = (kt) * 128;                                                 \
        const uint32_t sst = sbase + (stage) * STAGE_SZ;                            \
        _Pragma("unroll")                                                           \
        for (int j = 0; j < 2; j++) {                                               \
            const int c = tid + 512 * j;                                            \
            const int row = c >> 3, h = c & 7;                                      \
            cpasync16(sst + STG_A + row * ROWB + h * 16,                            \
                      pAh + (size_t)(m0 + row) * (KP * 2) + k0b + h * 16);          \
        }                                                                           \
        _Pragma("unroll")                                                           \
        for (int j = 0; j < 4; j++) {                                               \
            const int c = tid + 512 * j;                                            \
            const int row = c >> 3, h = c & 7;                                      \
            cpasync16(sst + STG_B + row * ROWB + h * 16,                            \
                      pBh + (size_t)(n0 + row) * (KP * 2) + k0b + h * 16);          \
        }                                                                           \
        asm volatile("cp.async.commit_group;" ::: "memory");                        \
    }

    LOAD_TILE(0, 0);
    LOAD_TILE(1, 1);

    const int lmat = lane >> 3, lr = lane & 7;       // ldmatrix lane roles
    int stage = 0;
    for (int kt = 0; kt < KT64; kt++) {
        asm volatile("cp.async.wait_group 1;" ::: "memory");   // tile kt resident
        __syncthreads();                                       // + compute(kt-1) done
        if (kt + 2 < KT64) {
            const int ns = (stage + 2 >= NSTAGE) ? stage + 2 - NSTAGE : stage + 2;
            LOAD_TILE(kt + 2, ns);
        } else {
            asm volatile("cp.async.commit_group;" ::: "memory");  // keep group count
        }

        const uint32_t s = sbase + stage * STAGE_SZ;
#pragma unroll
        for (int kk = 0; kk < 4; kk++) {
            const int h = kk * 2 + (lmat >> 1);
            uint32_t ah[2][4], bh[4][4];
#pragma unroll
            for (int mt = 0; mt < 2; mt++) {
                const int row = wm + mt * 16 + (lmat & 1) * 8 + lr;
                ldsm4(ah[mt], s + STG_A + row * ROWB + h * 16);
            }
#pragma unroll
            for (int np = 0; np < 4; np++) {
                const int row = wn + np * 16 + (lmat & 1) * 8 + lr;
                ldsm4(bh[np], s + STG_B + row * ROWB + h * 16);
            }
#pragma unroll
            for (int mt = 0; mt < 2; mt++)
#pragma unroll
                for (int nt = 0; nt < 8; nt++) {
                    const int np = nt >> 1, sub = nt & 1;
                    mma16816(acc[mt][nt], ah[mt], bh[np][sub], bh[np][sub + 2]);
                }
        }
        stage = (stage + 1 >= NSTAGE) ? 0 : stage + 1;
    }

    // epilogue
    if (mat < 7) {
        __half* dsth = xrelh + (size_t)mat * N * 256;
#pragma unroll
        for (int mt = 0; mt < 2; mt++) {
#pragma unroll
            for (int nt = 0; nt < 8; nt++) {
                const int c = wn + nt * 8 + 2 * (lane & 3);
                const int r0 = m0 + wm + mt * 16 + (lane >> 2);
                if (r0 < N)
                    *(__half2*)&dsth[(size_t)r0 * 256 + c] =
                        __floats2half2_rn(acc[mt][nt][0], acc[mt][nt][1]);
                const int r1 = r0 + 8;
                if (r1 < N)
                    *(__half2*)&dsth[(size_t)r1 * 256 + c] =
                        __floats2half2_rn(acc[mt][nt][2], acc[mt][nt][3]);
            }
        }
    } else {
#pragma unroll
        for (int mt = 0; mt < 2; mt++) {
#pragma unroll
            for (int nt = 0; nt < 8; nt++) {
                const int c = wn + nt * 8 + 2 * (lane & 3);
                const float bb0 = b1[c], bb1 = b1[c + 1];
                const int r0 = m0 + wm + mt * 16 + (lane >> 2);
                if (r0 < N)
                    *(float2*)&out1[(size_t)r0 * 256 + c] =
                        make_float2(acc[mt][nt][0] + bb0, acc[mt][nt][1] + bb1);
                const int r1 = r0 + 8;
                if (r1 < N)
                    *(float2*)&out1[(size_t)r1 * 256 + c] =
                        make_float2(acc[mt][nt][2] + bb0, acc[mt][nt][3] + bb1);
            }
        }
    }
}

// ---------------- layer-1 aggregation (atomic-free): warp per dst node, rel window -------
__global__ void __launch_bounds__(256) gather1_kernel(int N, int tlo, int thi) {
    const int d    = (blockIdx.x * 256 + threadIdx.x) >> 5;
    const int lane = threadIdx.x & 31;
    if (d >= N) return;
    const int beg = g_off[d], end = g_off[d + 1];
    float acc[8];
#pragma unroll
    for (int i = 0; i < 8; i++) acc[i] = 0.0f;
    for (int j = beg; j < end; j++) {
        const int p = g_csr[j];
        const int t = p >> 20;
        if (t < tlo || t > thi) continue;
        const int s = p & 0xFFFFF;
        const float w = g_invcnt[(size_t)t * N + d];
        const uint4 v = ((const uint4*)&g_xrelh[((size_t)t * N + s) * D_HID])[lane];
        const __half2* hp = (const __half2*)&v;
        const float2 f0 = __half22float2(hp[0]), f1 = __half22float2(hp[1]);
        const float2 f2 = __half22float2(hp[2]), f3 = __half22float2(hp[3]);
        acc[0] += w * f0.x; acc[1] += w * f0.y; acc[2] += w * f1.x; acc[3] += w * f1.y;
        acc[4] += w * f2.x; acc[5] += w * f2.y; acc[6] += w * f3.x; acc[7] += w * f3.y;
    }
    float* dstp = &g_out1[(size_t)d * D_HID + lane * 8];
    float4 o0 = *(float4*)dstp, o1 = *(float4*)(dstp + 4);
    o0.x += acc[0]; o0.y += acc[1]; o0.z += acc[2]; o0.w += acc[3];
    o1.x += acc[4]; o1.y += acc[5]; o1.z += acc[6]; o1.w += acc[7];
    *(float4*)dstp = o0; *(float4*)(dstp + 4) = o1;
}

// ---------------- layer 2: h=relu(out1); 16 dots per node ----------------
__global__ void __launch_bounds__(256) layer2_kernel(
    const float* __restrict__ w2rel, const float* __restrict__ w2root,
    const float* __restrict__ b2, float* __restrict__ out, int N)
{
    __shared__ float ws[16][D_HID];
    const int tid = threadIdx.x;
    for (int idx = tid; idx < 16 * D_HID; idx += 256) {
        const int o = idx >> 8, k = idx & 255;
        float v;
        if (o < 14) v = w2rel[((size_t)(o >> 1) * D_HID + k) * 2 + (o & 1)];
        else        v = w2root[(size_t)k * 2 + (o & 1)];
        ws[o][k] = v;
    }
    __syncthreads();
    const int warp = tid >> 5, lane = tid & 31;
    const int n = blockIdx.x * 8 + warp;
    if (n >= N) return;
    float hv[8];
#pragma unroll
    for (int i = 0; i < 8; i++)
        hv[i] = fmaxf(g_out1[(size_t)n * D_HID + lane + 32 * i], 0.0f);
#pragma unroll
    for (int o = 0; o < 16; o++) {
        float sacc = 0.0f;
#pragma unroll
        for (int i = 0; i < 8; i++) sacc += hv[i] * ws[o][lane + 32 * i];
#pragma unroll
        for (int off = 16; off; off >>= 1) sacc += __shfl_xor_sync(0xffffffffu, sacc, off);
        if (lane == 0) {
            if (o < 14) g_h2[((size_t)(o >> 1) * N + n) * 2 + (o & 1)] = sacc;
            else        out[(size_t)n * 2 + (o & 1)] = sacc + b2[o & 1];
        }
    }
}

// ---------------- layer-2 edge scatter (tiny; atomics fine) ----------------
__global__ void scatter2_kernel(float* __restrict__ out, int E, int N) {
    const int e = blockIdx.x * blockDim.x + threadIdx.x;
    if (e >= E) return;
    const int s = g_src[e], d = g_dst[e], t = g_et[e];
    const float w = g_invcnt[(size_t)t * N + d];
    const float2 v = *(const float2*)&g_h2[((size_t)t * N + s) * 2];
    asm volatile("red.global.add.v2.f32 [%0], {%1, %2};"
                 :: "l"(out + (size_t)d * 2), "f"(v.x * w), "f"(v.y * w)
                 : "memory");
}

// ---------------- launch ----------------
extern "C" void kernel_launch(void* const* d_in, const int* in_sizes, int n_in,
                              void* d_out, int out_size) {
    const float* x       = (const float*)d_in[0];
    const void*  ei      = d_in[1];
    const void*  et      = d_in[2];
    const float* w1_rel  = (const float*)d_in[3];
    const float* w1_root = (const float*)d_in[4];
    const float* b1      = (const float*)d_in[5];
    const float* w2_rel  = (const float*)d_in[6];
    const float* w2_root = (const float*)d_in[7];
    const float* b2      = (const float*)d_in[8];
    float* out = (float*)d_out;

    const int N = in_sizes[0] / D_IN;
    const int E = in_sizes[2];

    static __half *Ah_p = nullptr, *Bh_p = nullptr, *xrelh_p = nullptr;
    static float *out1_p = nullptr;
    static cudaStream_t s2 = nullptr;
    static cudaEvent_t evFork = nullptr, evW = nullptr, evX1 = nullptr,
                       evA = nullptr, evB = nullptr, evDone = nullptr;
    if (!Ah_p) {
        cudaGetSymbolAddress((void**)&Ah_p, g_Ah);
        cudaGetSymbolAddress((void**)&Bh_p, g_Bh);
        cudaGetSymbolAddress((void**)&xrelh_p, g_xrelh);
        cudaGetSymbolAddress((void**)&out1_p, g_out1);
        cudaFuncSetAttribute(hmma_gemm, cudaFuncAttributeMaxDynamicSharedMemorySize, GEMM_SMEM);
        cudaStreamCreateWithFlags(&s2, cudaStreamNonBlocking);
        cudaEventCreateWithFlags(&evFork, cudaEventDisableTiming);
        cudaEventCreateWithFlags(&evW, cudaEventDisableTiming);
        cudaEventCreateWithFlags(&evX1, cudaEventDisableTiming);
        cudaEventCreateWithFlags(&evA, cudaEventDisableTiming);
        cudaEventCreateWithFlags(&evB, cudaEventDisableTiming);
        cudaEventCreateWithFlags(&evDone, cudaEventDisableTiming);
    }

    const int HALF = MTILES / 2;           // 196 row tiles per half
    cudaEventRecord(evFork, 0);
    cudaStreamWaitEvent(s2, evFork, 0);

    // s2: weight transpose + upper-half X convert (hidden under main's work), then CSR
    dim3 gw((KP + 255) / 256, NMATS * 256);
    convert_w<<<gw, 256, 0, s2>>>(w1_rel, w1_root, Bh_p);
    cudaEventRecord(evW, s2);
    convert_x<<<HALF * 128, 256, 0, s2>>>(x, Ah_p, N, HALF * 128);
    cudaEventRecord(evX1, s2);

    detect_kernel<<<1, 128, 0, s2>>>((const unsigned int*)ei, (const unsigned int*)et, E);
    decode_kernel<<<(E + 255) / 256, 256, 0, s2>>>(ei, et, E);
    const int NC = N_RELS * N;
    zero_kernel<<<(NC + 255) / 256, 256, 0, s2>>>(NC, N);
    count_kernel<<<(E + 255) / 256, 256, 0, s2>>>(E, N);
    scan_kernel<<<1, 1024, 0, s2>>>(N);
    invcnt_kernel<<<(NC + 255) / 256, 256, 0, s2>>>(NC);
    fill_kernel<<<(E + 255) / 256, 256, 0, s2>>>(E);

    // main: lower-half X convert, then GEMM slices
    convert_x<<<HALF * 128, 256>>>(x, Ah_p, N, 0);
    cudaStreamWaitEvent(0, evW, 0);
    // GEMM-A1: mats 2..7, lower row half
    dim3 ggA1(6, HALF);
    hmma_gemm<<<ggA1, 512, GEMM_SMEM>>>(Ah_p, Bh_p, b1, xrelh_p, out1_p, N, 2, 0);
    cudaStreamWaitEvent(0, evX1, 0);
    // GEMM-A2: mats 2..7, upper row half
    dim3 ggA2(6, MTILES - HALF);
    hmma_gemm<<<ggA2, 512, GEMM_SMEM>>>(Ah_p, Bh_p, b1, xrelh_p, out1_p, N, 2, HALF);
    cudaEventRecord(evA, 0);
    // GEMM-B: mats 0..1, all rows — concurrent with s2's gather of rels 2..6
    dim3 ggB(2, MTILES);
    hmma_gemm<<<ggB, 512, GEMM_SMEM>>>(Ah_p, Bh_p, b1, xrelh_p, out1_p, N, 0, 0);
    cudaEventRecord(evB, 0);

    // s2: gather rels 2..6 under GEMM-B, then the exposed tail (rels 0..1)
    cudaStreamWaitEvent(s2, evA, 0);
    gather1_kernel<<<(N * 32 + 255) / 256, 256, 0, s2>>>(N, 2, 6);
    cudaStreamWaitEvent(s2, evB, 0);
    gather1_kernel<<<(N * 32 + 255) / 256, 256, 0, s2>>>(N, 0, 1);

    // s2: layer 2 + scatter (depend on completed out1 and CSR data)
    layer2_kernel<<<(N + 7) / 8, 256, 0, s2>>>(w2_rel, w2_root, b2, out, N);
    scatter2_kernel<<<(E + 255) / 256, 256, 0, s2>>>(out, E, N);

    // join back to the capture stream
    cudaEventRecord(evDone, s2);
    cudaStreamWaitEvent(0, evDone, 0);
}

// round 16
// speedup vs baseline: 1.0417x; 1.0002x over previous
#include <cuda_runtime.h>
#include <cuda_fp16.h>
#include <cstdint>
#include <cstddef>

#define D_IN   788
#define D_HID  256
#define N_RELS 7
#define MAXN   50000
#define MAXE   800000
#define KP     832          // D_IN padded to 13*64
#define KT64   13           // K chunks of 64
#define MP     50176        // 392*128 padded rows
#define MTILES 392
#define NMATS  8            // 7 relations + root

// ---------------- scratch (device globals; no allocations allowed) ----------------
__device__ __align__(16) __half g_Ah[(size_t)MP * KP];            // 83.5 MB
__device__ __align__(16) __half g_Bh[(size_t)NMATS * 256 * KP];   // 3.4 MB
__device__ __align__(16) __half g_xrelh[(size_t)N_RELS * MAXN * D_HID];  // 179 MB (fp16)
__device__ __align__(16) float g_out1[(size_t)MAXN * D_HID];             // 51 MB
__device__ __align__(16) float g_h2[(size_t)N_RELS * MAXN * 2];
__device__ float g_invcnt[(size_t)N_RELS * MAXN];
__device__ int   g_src[MAXE];
__device__ int   g_dst[MAXE];
__device__ int   g_et[MAXE];
__device__ int   g_deg[MAXN];
__device__ int   g_cursor[MAXN];
__device__ int   g_off[MAXN + 1];
__device__ int   g_csr[MAXE];        // src | (et<<20)
__device__ int   g_flags[2];

// ---------------- helpers ----------------
__device__ __forceinline__ uint32_t smem_u32(const void* p) {
    uint32_t a;
    asm("{ .reg .u64 t; cvta.to.shared.u64 t, %1; cvt.u32.u64 %0, t; }" : "=r"(a) : "l"(p));
    return a;
}
__device__ __forceinline__ void cpasync16(uint32_t saddr, const void* g) {
    asm volatile("cp.async.ca.shared.global [%0], [%1], 16;" :: "r"(saddr), "l"(g));
}
__device__ __forceinline__ void ldsm4(uint32_t* r, uint32_t addr) {
    asm volatile("ldmatrix.sync.aligned.m8n8.x4.shared.b16 {%0,%1,%2,%3}, [%4];"
                 : "=r"(r[0]), "=r"(r[1]), "=r"(r[2]), "=r"(r[3]) : "r"(addr));
}
__device__ __forceinline__ void mma16816(float* d, const uint32_t* a, uint32_t b0, uint32_t b1) {
    asm volatile("mma.sync.aligned.m16n8k16.row.col.f32.f16.f16.f32 "
                 "{%0,%1,%2,%3}, {%4,%5,%6,%7}, {%8,%9}, {%0,%1,%2,%3};"
                 : "+f"(d[0]), "+f"(d[1]), "+f"(d[2]), "+f"(d[3])
                 : "r"(a[0]), "r"(a[1]), "r"(a[2]), "r"(a[3]), "r"(b0), "r"(b1));
}

// ---------------- fp32 -> fp16 of X rows [rowbase, rowbase+gridDim.x) ----------------
__global__ void __launch_bounds__(256) convert_x(const float* __restrict__ x,
                          __half* __restrict__ Ah, int N, int rowbase) {
    const int row = rowbase + blockIdx.x;
    const int k = threadIdx.x * 4;
    if (k >= KP) return;
    float4 v = make_float4(0.f, 0.f, 0.f, 0.f);
    if (row < N && k < D_IN) v = *(const float4*)&x[(size_t)row * D_IN + k];
    __half2 h01 = make_half2(__float2half(v.x), __float2half(v.y));
    __half2 h23 = make_half2(__float2half(v.z), __float2half(v.w));
    const size_t o = (size_t)row * KP + k;
    *(__half2*)&Ah[o] = h01; *(__half2*)&Ah[o + 2] = h23;
}

// ---------------- transpose W1: Bt[mat*256+n][k] fp16 ----------------
__global__ void convert_w(const float* __restrict__ w1_rel, const float* __restrict__ w1_root,
                          __half* __restrict__ Bh) {
    const int r = blockIdx.y;            // 0..2047 -> mat = r>>8, n = r&255
    const int mat = r >> 8, n = r & 255;
    const int k = blockIdx.x * 256 + threadIdx.x;
    if (k >= KP) return;
    float v = 0.0f;
    if (k < D_IN) {
        if (mat < 7) v = w1_rel[((size_t)mat * D_IN + k) * 256 + n];
        else         v = w1_root[(size_t)k * 256 + n];
    }
    Bh[(size_t)r * KP + k] = __float2half(v);
}

// ---------------- dtype detection + index decode ----------------
__global__ void detect_kernel(const unsigned int* ei, const unsigned int* et, int E) {
    __shared__ int bad_ei, bad_et;
    if (threadIdx.x == 0) { bad_ei = 0; bad_et = 0; }
    __syncthreads();
    int n = E < 64 ? E : 64;
    if ((int)threadIdx.x < n) {
        if (ei[2 * threadIdx.x + 1] != 0u) bad_ei = 1;
        if (et[2 * threadIdx.x + 1] != 0u) bad_et = 1;
    }
    __syncthreads();
    if (threadIdx.x == 0) { g_flags[0] = !bad_ei; g_flags[1] = !bad_et; }
}

__global__ void decode_kernel(const void* ei, const void* et, int E) {
    int e = blockIdx.x * blockDim.x + threadIdx.x;
    if (e >= E) return;
    long long s, d, t;
    if (g_flags[0]) {
        const long long* p = (const long long*)ei;
        s = p[e]; d = p[(size_t)E + e];
    } else {
        const int* p = (const int*)ei;
        s = p[e]; d = p[(size_t)E + e];
    }
    if (g_flags[1]) t = ((const long long*)et)[e];
    else            t = ((const int*)et)[e];
    g_src[e] = (int)s; g_dst[e] = (int)d; g_et[e] = (int)t;
}

// ---------------- degree counting + CSR build ----------------
__global__ void zero_kernel(int NC, int N) {
    int i = blockIdx.x * blockDim.x + threadIdx.x;
    if (i < NC) g_invcnt[i] = 0.0f;
    if (i < N) { g_deg[i] = 0; g_cursor[i] = 0; }
}
__global__ void count_kernel(int E, int N) {
    int e = blockIdx.x * blockDim.x + threadIdx.x;
    if (e >= E) return;
    const int d = g_dst[e];
    atomicAdd(&g_invcnt[(size_t)g_et[e] * N + d], 1.0f);
    atomicAdd(&g_deg[d], 1);
}
__global__ void invcnt_kernel(int n) {
    int i = blockIdx.x * blockDim.x + threadIdx.x;
    if (i < n) g_invcnt[i] = 1.0f / fmaxf(g_invcnt[i], 1.0f);
}
// single-block exclusive scan of g_deg[0..N) -> g_off
__global__ void __launch_bounds__(1024) scan_kernel(int N) {
    __shared__ int ssum[1024];
    const int t = threadIdx.x;
    const int chunk = (N + 1023) / 1024;
    const int start = t * chunk;
    const int end = min(start + chunk, N);
    int s = 0;
    for (int i = start; i < end; i++) s += g_deg[i];
    ssum[t] = s;
    __syncthreads();
    for (int off = 1; off < 1024; off <<= 1) {
        int u = (t >= off) ? ssum[t - off] : 0;
        __syncthreads();
        ssum[t] += u;
        __syncthreads();
    }
    int run = ssum[t] - s;          // exclusive prefix of this chunk
    for (int i = start; i < end; i++) { g_off[i] = run; run += g_deg[i]; }
    if (t == 1023) g_off[N] = ssum[1023];
}
__global__ void fill_kernel(int E) {
    int e = blockIdx.x * blockDim.x + threadIdx.x;
    if (e >= E) return;
    const int d = g_dst[e];
    const int pos = atomicAdd(&g_cursor[d], 1);
    g_csr[g_off[d] + pos] = g_src[e] | (g_et[e] << 20);
}

// ---------------- HMMA GEMM slice: mats [mat0, ...), row tiles [row0, ...) --------------
#define ROWB     144
#define ARR_A    (128 * ROWB)      // 18432
#define ARR_B    (256 * ROWB)      // 36864
#define STG_A    0
#define STG_B    ARR_A
#define STAGE_SZ (ARR_A + ARR_B)   // 55296
#define NSTAGE   3
#define GEMM_SMEM (NSTAGE * STAGE_SZ)  // 165888

__global__ void __launch_bounds__(512, 1) hmma_gemm(
    const __half* __restrict__ Ah, const __half* __restrict__ Bh,
    const float* __restrict__ b1, __half* __restrict__ xrelh, float* __restrict__ out1,
    int N, int mat0, int row0)
{
    extern __shared__ char smem[];
    const uint32_t sbase = smem_u32(smem);
    const int mat = mat0 + blockIdx.x;
    const int m0 = (row0 + blockIdx.y) * 128;
    const int n0 = mat * 256;                        // B row offset for this matrix
    const int tid = threadIdx.x;
    const int warp = tid >> 5, lane = tid & 31;
    const int wm = (warp & 3) * 32, wn = (warp >> 2) * 64;

    float acc[2][8][4];
#pragma unroll
    for (int i = 0; i < 2; i++)
#pragma unroll
        for (int j = 0; j < 8; j++)
#pragma unroll
            for (int q = 0; q < 4; q++) acc[i][j][q] = 0.0f;

    const char* pAh = (const char*)Ah;
    const char* pBh = (const char*)Bh;

// chunk c = tid + 512*j: row = c>>3, h = c&7. A: j<2 (1024 chunks), B: j<4 (2048 chunks)
#define LOAD_TILE(kt, stage)                                                        \
    {                                                                               \
        const int k0b = (kt) * 128;                                                 \
        const uint32_t sst = sbase + (stage) * STAGE_SZ;                            \
        _Pragma("unroll")                                                           \
        for (int j = 0; j < 2; j++) {                                               \
            const int c = tid + 512 * j;                                            \
            const int row = c >> 3, h = c & 7;                                      \
            cpasync16(sst + STG_A + row * ROWB + h * 16,                            \
                      pAh + (size_t)(m0 + row) * (KP * 2) + k0b + h * 16);          \
        }                                                                           \
        _Pragma("unroll")                                                           \
        for (int j = 0; j < 4; j++) {                                               \
            const int c = tid + 512 * j;                                            \
            const int row = c >> 3, h = c & 7;                                      \
            cpasync16(sst + STG_B + row * ROWB + h * 16,                            \
                      pBh + (size_t)(n0 + row) * (KP * 2) + k0b + h * 16);          \
        }                                                                           \
        asm volatile("cp.async.commit_group;" ::: "memory");                        \
    }

    LOAD_TILE(0, 0);
    LOAD_TILE(1, 1);

    const int lmat = lane >> 3, lr = lane & 7;       // ldmatrix lane roles
    int stage = 0;
    for (int kt = 0; kt < KT64; kt++) {
        asm volatile("cp.async.wait_group 1;" ::: "memory");   // tile kt resident
        __syncthreads();                                       // + compute(kt-1) done
        if (kt + 2 < KT64) {
            const int ns = (stage + 2 >= NSTAGE) ? stage + 2 - NSTAGE : stage + 2;
            LOAD_TILE(kt + 2, ns);
        } else {
            asm volatile("cp.async.commit_group;" ::: "memory");  // keep group count
        }

        const uint32_t s = sbase + stage * STAGE_SZ;
#pragma unroll
        for (int kk = 0; kk < 4; kk++) {
            const int h = kk * 2 + (lmat >> 1);
            uint32_t ah[2][4], bh[4][4];
#pragma unroll
            for (int mt = 0; mt < 2; mt++) {
                const int row = wm + mt * 16 + (lmat & 1) * 8 + lr;
                ldsm4(ah[mt], s + STG_A + row * ROWB + h * 16);
            }
#pragma unroll
            for (int np = 0; np < 4; np++) {
                const int row = wn + np * 16 + (lmat & 1) * 8 + lr;
                ldsm4(bh[np], s + STG_B + row * ROWB + h * 16);
            }
#pragma unroll
            for (int mt = 0; mt < 2; mt++)
#pragma unroll
                for (int nt = 0; nt < 8; nt++) {
                    const int np = nt >> 1, sub = nt & 1;
                    mma16816(acc[mt][nt], ah[mt], bh[np][sub], bh[np][sub + 2]);
                }
        }
        stage = (stage + 1 >= NSTAGE) ? 0 : stage + 1;
    }

    // epilogue
    if (mat < 7) {
        __half* dsth = xrelh + (size_t)mat * N * 256;
#pragma unroll
        for (int mt = 0; mt < 2; mt++) {
#pragma unroll
            for (int nt = 0; nt < 8; nt++) {
                const int c = wn + nt * 8 + 2 * (lane & 3);
                const int r0 = m0 + wm + mt * 16 + (lane >> 2);
                if (r0 < N)
                    *(__half2*)&dsth[(size_t)r0 * 256 + c] =
                        __floats2half2_rn(acc[mt][nt][0], acc[mt][nt][1]);
                const int r1 = r0 + 8;
                if (r1 < N)
                    *(__half2*)&dsth[(size_t)r1 * 256 + c] =
                        __floats2half2_rn(acc[mt][nt][2], acc[mt][nt][3]);
            }
        }
    } else {
#pragma unroll
        for (int mt = 0; mt < 2; mt++) {
#pragma unroll
            for (int nt = 0; nt < 8; nt++) {
                const int c = wn + nt * 8 + 2 * (lane & 3);
                const float bb0 = b1[c], bb1 = b1[c + 1];
                const int r0 = m0 + wm + mt * 16 + (lane >> 2);
                if (r0 < N)
                    *(float2*)&out1[(size_t)r0 * 256 + c] =
                        make_float2(acc[mt][nt][0] + bb0, acc[mt][nt][1] + bb1);
                const int r1 = r0 + 8;
                if (r1 < N)
                    *(float2*)&out1[(size_t)r1 * 256 + c] =
                        make_float2(acc[mt][nt][2] + bb0, acc[mt][nt][3] + bb1);
            }
        }
    }
}

// ---------------- layer-1 aggregation (atomic-free): warp per dst node, rel window -------
__global__ void __launch_bounds__(256) gather1_kernel(int N, int tlo, int thi) {
    const int d    = (blockIdx.x * 256 + threadIdx.x) >> 5;
    const int lane = threadIdx.x & 31;
    if (d >= N) return;
    const int beg = g_off[d], end = g_off[d + 1];
    float acc[8];
#pragma unroll
    for (int i = 0; i < 8; i++) acc[i] = 0.0f;
    for (int j = beg; j < end; j++) {
        const int p = g_csr[j];
        const int t = p >> 20;
        if (t < tlo || t > thi) continue;
        const int s = p & 0xFFFFF;
        const float w = g_invcnt[(size_t)t * N + d];
        const uint4 v = ((const uint4*)&g_xrelh[((size_t)t * N + s) * D_HID])[lane];
        const __half2* hp = (const __half2*)&v;
        const float2 f0 = __half22float2(hp[0]), f1 = __half22float2(hp[1]);
        const float2 f2 = __half22float2(hp[2]), f3 = __half22float2(hp[3]);
        acc[0] += w * f0.x; acc[1] += w * f0.y; acc[2] += w * f1.x; acc[3] += w * f1.y;
        acc[4] += w * f2.x; acc[5] += w * f2.y; acc[6] += w * f3.x; acc[7] += w * f3.y;
    }
    float* dstp = &g_out1[(size_t)d * D_HID + lane * 8];
    float4 o0 = *(float4*)dstp, o1 = *(float4*)(dstp + 4);
    o0.x += acc[0]; o0.y += acc[1]; o0.z += acc[2]; o0.w += acc[3];
    o1.x += acc[4]; o1.y += acc[5]; o1.z += acc[6]; o1.w += acc[7];
    *(float4*)dstp = o0; *(float4*)(dstp + 4) = o1;
}

// ---------------- fused tail: gather rels [0,1] + relu + layer-2 transforms --------------
// warp per node; out1 row finalized in registers (no write-back) and consumed directly.
__global__ void __launch_bounds__(256) gather_tail_l2_kernel(
    const float* __restrict__ w2rel, const float* __restrict__ w2root,
    const float* __restrict__ b2, float* __restrict__ out, int N)
{
    __shared__ float ws[16][D_HID];
    const int tid = threadIdx.x;
    for (int idx = tid; idx < 16 * D_HID; idx += 256) {
        const int o = idx >> 8, k = idx & 255;
        float v;
        if (o < 14) v = w2rel[((size_t)(o >> 1) * D_HID + k) * 2 + (o & 1)];
        else        v = w2root[(size_t)k * 2 + (o & 1)];
        ws[o][k] = v;
    }
    __syncthreads();

    const int d    = (blockIdx.x * 256 + tid) >> 5;
    const int lane = tid & 31;
    if (d >= N) return;

    // out1 row (root + b1 + rels 2..6); lane owns cols lane*8 .. lane*8+7
    float acc[8];
    {
        const float4 o0 = *(const float4*)&g_out1[(size_t)d * D_HID + lane * 8];
        const float4 o1 = *(const float4*)&g_out1[(size_t)d * D_HID + lane * 8 + 4];
        acc[0] = o0.x; acc[1] = o0.y; acc[2] = o0.z; acc[3] = o0.w;
        acc[4] = o1.x; acc[5] = o1.y; acc[6] = o1.z; acc[7] = o1.w;
    }
    // tail gather: rels 0..1
    const int beg = g_off[d], end = g_off[d + 1];
    for (int j = beg; j < end; j++) {
        const int p = g_csr[j];
        const int t = p >> 20;
        if (t > 1) continue;
        const int s = p & 0xFFFFF;
        const float w = g_invcnt[(size_t)t * N + d];
        const uint4 v = ((const uint4*)&g_xrelh[((size_t)t * N + s) * D_HID])[lane];
        const __half2* hp = (const __half2*)&v;
        const float2 f0 = __half22float2(hp[0]), f1 = __half22float2(hp[1]);
        const float2 f2 = __half22float2(hp[2]), f3 = __half22float2(hp[3]);
        acc[0] += w * f0.x; acc[1] += w * f0.y; acc[2] += w * f1.x; acc[3] += w * f1.y;
        acc[4] += w * f2.x; acc[5] += w * f2.y; acc[6] += w * f3.x; acc[7] += w * f3.y;
    }
    // relu
#pragma unroll
    for (int i = 0; i < 8; i++) acc[i] = fmaxf(acc[i], 0.0f);

    // layer-2: 16 dots (7 rels x 2 + root x 2); lane's columns are lane*8 .. lane*8+7
#pragma unroll
    for (int o = 0; o < 16; o++) {
        float sacc = 0.0f;
#pragma unroll
        for (int i = 0; i < 8; i++) sacc += acc[i] * ws[o][lane * 8 + i];
#pragma unroll
        for (int off = 16; off; off >>= 1) sacc += __shfl_xor_sync(0xffffffffu, sacc, off);
        if (lane == 0) {
            if (o < 14) g_h2[((size_t)(o >> 1) * N + d) * 2 + (o & 1)] = sacc;
            else        out[(size_t)d * 2 + (o & 1)] = sacc + b2[o & 1];
        }
    }
}

// ---------------- layer-2 edge scatter (tiny; atomics fine) ----------------
__global__ void scatter2_kernel(float* __restrict__ out, int E, int N) {
    const int e = blockIdx.x * blockDim.x + threadIdx.x;
    if (e >= E) return;
    const int s = g_src[e], d = g_dst[e], t = g_et[e];
    const float w = g_invcnt[(size_t)t * N + d];
    const float2 v = *(const float2*)&g_h2[((size_t)t * N + s) * 2];
    asm volatile("red.global.add.v2.f32 [%0], {%1, %2};"
                 :: "l"(out + (size_t)d * 2), "f"(v.x * w), "f"(v.y * w)
                 : "memory");
}

// ---------------- launch ----------------
extern "C" void kernel_launch(void* const* d_in, const int* in_sizes, int n_in,
                              void* d_out, int out_size) {
    const float* x       = (const float*)d_in[0];
    const void*  ei      = d_in[1];
    const void*  et      = d_in[2];
    const float* w1_rel  = (const float*)d_in[3];
    const float* w1_root = (const float*)d_in[4];
    const float* b1      = (const float*)d_in[5];
    const float* w2_rel  = (const float*)d_in[6];
    const float* w2_root = (const float*)d_in[7];
    const float* b2      = (const float*)d_in[8];
    float* out = (float*)d_out;

    const int N = in_sizes[0] / D_IN;
    const int E = in_sizes[2];

    static __half *Ah_p = nullptr, *Bh_p = nullptr, *xrelh_p = nullptr;
    static float *out1_p = nullptr;
    static cudaStream_t s2 = nullptr;
    static cudaEvent_t evFork = nullptr, evW = nullptr, evX1 = nullptr,
                       evA = nullptr, evB = nullptr, evDone = nullptr;
    if (!Ah_p) {
        cudaGetSymbolAddress((void**)&Ah_p, g_Ah);
        cudaGetSymbolAddress((void**)&Bh_p, g_Bh);
        cudaGetSymbolAddress((void**)&xrelh_p, g_xrelh);
        cudaGetSymbolAddress((void**)&out1_p, g_out1);
        cudaFuncSetAttribute(hmma_gemm, cudaFuncAttributeMaxDynamicSharedMemorySize, GEMM_SMEM);
        cudaStreamCreateWithFlags(&s2, cudaStreamNonBlocking);
        cudaEventCreateWithFlags(&evFork, cudaEventDisableTiming);
        cudaEventCreateWithFlags(&evW, cudaEventDisableTiming);
        cudaEventCreateWithFlags(&evX1, cudaEventDisableTiming);
        cudaEventCreateWithFlags(&evA, cudaEventDisableTiming);
        cudaEventCreateWithFlags(&evB, cudaEventDisableTiming);
        cudaEventCreateWithFlags(&evDone, cudaEventDisableTiming);
    }

    const int HALF = MTILES / 2;           // 196 row tiles per half
    cudaEventRecord(evFork, 0);
    cudaStreamWaitEvent(s2, evFork, 0);

    // s2: weight transpose + upper-half X convert (hidden under main's work), then CSR
    dim3 gw((KP + 255) / 256, NMATS * 256);
    convert_w<<<gw, 256, 0, s2>>>(w1_rel, w1_root, Bh_p);
    cudaEventRecord(evW, s2);
    convert_x<<<HALF * 128, 256, 0, s2>>>(x, Ah_p, N, HALF * 128);
    cudaEventRecord(evX1, s2);

    detect_kernel<<<1, 128, 0, s2>>>((const unsigned int*)ei, (const unsigned int*)et, E);
    decode_kernel<<<(E + 255) / 256, 256, 0, s2>>>(ei, et, E);
    const int NC = N_RELS * N;
    zero_kernel<<<(NC + 255) / 256, 256, 0, s2>>>(NC, N);
    count_kernel<<<(E + 255) / 256, 256, 0, s2>>>(E, N);
    scan_kernel<<<1, 1024, 0, s2>>>(N);
    invcnt_kernel<<<(NC + 255) / 256, 256, 0, s2>>>(NC);
    fill_kernel<<<(E + 255) / 256, 256, 0, s2>>>(E);

    // main: lower-half X convert, then GEMM slices
    convert_x<<<HALF * 128, 256>>>(x, Ah_p, N, 0);
    cudaStreamWaitEvent(0, evW, 0);
    dim3 ggA1(6, HALF);
    hmma_gemm<<<ggA1, 512, GEMM_SMEM>>>(Ah_p, Bh_p, b1, xrelh_p, out1_p, N, 2, 0);
    cudaStreamWaitEvent(0, evX1, 0);
    dim3 ggA2(6, MTILES - HALF);
    hmma_gemm<<<ggA2, 512, GEMM_SMEM>>>(Ah_p, Bh_p, b1, xrelh_p, out1_p, N, 2, HALF);
    cudaEventRecord(evA, 0);
    dim3 ggB(2, MTILES);
    hmma_gemm<<<ggB, 512, GEMM_SMEM>>>(Ah_p, Bh_p, b1, xrelh_p, out1_p, N, 0, 0);
    cudaEventRecord(evB, 0);

    // s2: gather rels 2..6 under GEMM-B, then fused tail (rels 0..1 + relu + layer2)
    cudaStreamWaitEvent(s2, evA, 0);
    gather1_kernel<<<(N * 32 + 255) / 256, 256, 0, s2>>>(N, 2, 6);
    cudaStreamWaitEvent(s2, evB, 0);
    gather_tail_l2_kernel<<<(N * 32 + 255) / 256, 256, 0, s2>>>(w2_rel, w2_root, b2, out, N);
    scatter2_kernel<<<(E + 255) / 256, 256, 0, s2>>>(out, E, N);

    // join back to the capture stream
    cudaEventRecord(evDone, s2);
    cudaStreamWaitEvent(0, evDone, 0);
}

// round 17
// speedup vs baseline: 1.0419x; 1.0002x over previous
#include <cuda_runtime.h>
#include <cuda_fp16.h>
#include <cstdint>
#include <cstddef>

#define D_IN   788
#define D_HID  256
#define N_RELS 7
#define MAXN   50000
#define MAXE   800000
#define KP     832          // D_IN padded to 13*64
#define KT64   13           // K chunks of 64
#define MP     50176        // 392*128 padded rows
#define MTILES 392
#define NMATS  8            // 7 relations + root

// ---------------- scratch (device globals; no allocations allowed) ----------------
__device__ __align__(16) __half g_Ah[(size_t)MP * KP];            // 83.5 MB
__device__ __align__(16) __half g_Bh[(size_t)NMATS * 256 * KP];   // 3.4 MB
__device__ __align__(16) __half g_xrelh[(size_t)N_RELS * MAXN * D_HID];  // 179 MB (fp16)
__device__ __align__(16) float g_out1[(size_t)MAXN * D_HID];             // 51 MB
__device__ __align__(16) float g_h2[(size_t)N_RELS * MAXN * 2];
__device__ float g_invcnt[(size_t)N_RELS * MAXN];
__device__ int   g_src[MAXE];
__device__ int   g_dst[MAXE];
__device__ int   g_et[MAXE];
__device__ int   g_deg[MAXN];
__device__ int   g_cursor[MAXN];
__device__ int   g_off[MAXN + 1];
__device__ int   g_csr[MAXE];        // src | (et<<20)
__device__ int   g_flags[2];

// ---------------- helpers ----------------
__device__ __forceinline__ uint32_t smem_u32(const void* p) {
    uint32_t a;
    asm("{ .reg .u64 t; cvta.to.shared.u64 t, %1; cvt.u32.u64 %0, t; }" : "=r"(a) : "l"(p));
    return a;
}
__device__ __forceinline__ void cpasync16(uint32_t saddr, const void* g) {
    asm volatile("cp.async.ca.shared.global [%0], [%1], 16;" :: "r"(saddr), "l"(g));
}
__device__ __forceinline__ void ldsm4(uint32_t* r, uint32_t addr) {
    asm volatile("ldmatrix.sync.aligned.m8n8.x4.shared.b16 {%0,%1,%2,%3}, [%4];"
                 : "=r"(r[0]), "=r"(r[1]), "=r"(r[2]), "=r"(r[3]) : "r"(addr));
}
__device__ __forceinline__ void mma16816(float* d, const uint32_t* a, uint32_t b0, uint32_t b1) {
    asm volatile("mma.sync.aligned.m16n8k16.row.col.f32.f16.f16.f32 "
                 "{%0,%1,%2,%3}, {%4,%5,%6,%7}, {%8,%9}, {%0,%1,%2,%3};"
                 : "+f"(d[0]), "+f"(d[1]), "+f"(d[2]), "+f"(d[3])
                 : "r"(a[0]), "r"(a[1]), "r"(a[2]), "r"(a[3]), "r"(b0), "r"(b1));
}

// ---------------- fp32 -> fp16 of X rows [rowbase, rowbase+gridDim.x) ----------------
__global__ void __launch_bounds__(256) convert_x(const float* __restrict__ x,
                          __half* __restrict__ Ah, int N, int rowbase) {
    const int row = rowbase + blockIdx.x;
    const int k = threadIdx.x * 4;
    if (k >= KP) return;
    float4 v = make_float4(0.f, 0.f, 0.f, 0.f);
    if (row < N && k < D_IN) v = *(const float4*)&x[(size_t)row * D_IN + k];
    __half2 h01 = make_half2(__float2half(v.x), __float2half(v.y));
    __half2 h23 = make_half2(__float2half(v.z), __float2half(v.w));
    const size_t o = (size_t)row * KP + k;
    *(__half2*)&Ah[o] = h01; *(__half2*)&Ah[o + 2] = h23;
}

// ---------------- transpose W1: Bt[mat*256+n][k] fp16 ----------------
__global__ void convert_w(const float* __restrict__ w1_rel, const float* __restrict__ w1_root,
                          __half* __restrict__ Bh) {
    const int r = blockIdx.y;            // 0..2047 -> mat = r>>8, n = r&255
    const int mat = r >> 8, n = r & 255;
    const int k = blockIdx.x * 256 + threadIdx.x;
    if (k >= KP) return;
    float v = 0.0f;
    if (k < D_IN) {
        if (mat < 7) v = w1_rel[((size_t)mat * D_IN + k) * 256 + n];
        else         v = w1_root[(size_t)k * 256 + n];
    }
    Bh[(size_t)r * KP + k] = __float2half(v);
}

// ---------------- dtype detection + index decode ----------------
__global__ void detect_kernel(const unsigned int* ei, const unsigned int* et, int E) {
    __shared__ int bad_ei, bad_et;
    if (threadIdx.x == 0) { bad_ei = 0; bad_et = 0; }
    __syncthreads();
    int n = E < 64 ? E : 64;
    if ((int)threadIdx.x < n) {
        if (ei[2 * threadIdx.x + 1] != 0u) bad_ei = 1;
        if (et[2 * threadIdx.x + 1] != 0u) bad_et = 1;
    }
    __syncthreads();
    if (threadIdx.x == 0) { g_flags[0] = !bad_ei; g_flags[1] = !bad_et; }
}

__global__ void decode_kernel(const void* ei, const void* et, int E) {
    int e = blockIdx.x * blockDim.x + threadIdx.x;
    if (e >= E) return;
    long long s, d, t;
    if (g_flags[0]) {
        const long long* p = (const long long*)ei;
        s = p[e]; d = p[(size_t)E + e];
    } else {
        const int* p = (const int*)ei;
        s = p[e]; d = p[(size_t)E + e];
    }
    if (g_flags[1]) t = ((const long long*)et)[e];
    else            t = ((const int*)et)[e];
    g_src[e] = (int)s; g_dst[e] = (int)d; g_et[e] = (int)t;
}

// ---------------- degree counting + CSR build ----------------
__global__ void zero_kernel(int NC, int N) {
    int i = blockIdx.x * blockDim.x + threadIdx.x;
    if (i < NC) g_invcnt[i] = 0.0f;
    if (i < N) { g_deg[i] = 0; g_cursor[i] = 0; }
}
__global__ void count_kernel(int E, int N) {
    int e = blockIdx.x * blockDim.x + threadIdx.x;
    if (e >= E) return;
    const int d = g_dst[e];
    atomicAdd(&g_invcnt[(size_t)g_et[e] * N + d], 1.0f);
    atomicAdd(&g_deg[d], 1);
}
__global__ void invcnt_kernel(int n) {
    int i = blockIdx.x * blockDim.x + threadIdx.x;
    if (i < n) g_invcnt[i] = 1.0f / fmaxf(g_invcnt[i], 1.0f);
}
// single-block exclusive scan of g_deg[0..N) -> g_off
__global__ void __launch_bounds__(1024) scan_kernel(int N) {
    __shared__ int ssum[1024];
    const int t = threadIdx.x;
    const int chunk = (N + 1023) / 1024;
    const int start = t * chunk;
    const int end = min(start + chunk, N);
    int s = 0;
    for (int i = start; i < end; i++) s += g_deg[i];
    ssum[t] = s;
    __syncthreads();
    for (int off = 1; off < 1024; off <<= 1) {
        int u = (t >= off) ? ssum[t - off] : 0;
        __syncthreads();
        ssum[t] += u;
        __syncthreads();
    }
    int run = ssum[t] - s;          // exclusive prefix of this chunk
    for (int i = start; i < end; i++) { g_off[i] = run; run += g_deg[i]; }
    if (t == 1023) g_off[N] = ssum[1023];
}
__global__ void fill_kernel(int E) {
    int e = blockIdx.x * blockDim.x + threadIdx.x;
    if (e >= E) return;
    const int d = g_dst[e];
    const int pos = atomicAdd(&g_cursor[d], 1);
    g_csr[g_off[d] + pos] = g_src[e] | (g_et[e] << 20);
}

// ---------------- HMMA GEMM slice: mats [mat0, ...), row tiles [row0, ...) --------------
#define ROWB     144
#define ARR_A    (128 * ROWB)      // 18432
#define ARR_B    (256 * ROWB)      // 36864
#define STG_A    0
#define STG_B    ARR_A
#define STAGE_SZ (ARR_A + ARR_B)   // 55296
#define NSTAGE   3
#define GEMM_SMEM (NSTAGE * STAGE_SZ)  // 165888

__global__ void __launch_bounds__(512, 1) hmma_gemm(
    const __half* __restrict__ Ah, const __half* __restrict__ Bh,
    const float* __restrict__ b1, __half* __restrict__ xrelh, float* __restrict__ out1,
    int N, int mat0, int row0)
{
    extern __shared__ char smem[];
    const uint32_t sbase = smem_u32(smem);
    const int mat = mat0 + blockIdx.x;
    const int m0 = (row0 + blockIdx.y) * 128;
    const int n0 = mat * 256;                        // B row offset for this matrix
    const int tid = threadIdx.x;
    const int warp = tid >> 5, lane = tid & 31;
    const int wm = (warp & 3) * 32, wn = (warp >> 2) * 64;

    float acc[2][8][4];
#pragma unroll
    for (int i = 0; i < 2; i++)
#pragma unroll
        for (int j = 0; j < 8; j++)
#pragma unroll
            for (int q = 0; q < 4; q++) acc[i][j][q] = 0.0f;

    const char* pAh = (const char*)Ah;
    const char* pBh = (const char*)Bh;

// chunk c = tid + 512*j: row = c>>3, h = c&7. A: j<2 (1024 chunks), B: j<4 (2048 chunks)
#define LOAD_TILE(kt, stage)                                                        \
    {                                                                               \
        const int k0b = (kt) * 128;                                                 \
        const uint32_t sst = sbase + (stage) * STAGE_SZ;                            \
        _Pragma("unroll")                                                           \
        for (int j = 0; j < 2; j++) {                                               \
            const int c = tid + 512 * j;                                            \
            const int row = c >> 3, h = c & 7;                                      \
            cpasync16(sst + STG_A + row * ROWB + h * 16,                            \
                      pAh + (size_t)(m0 + row) * (KP * 2) + k0b + h * 16);          \
        }                                                                           \
        _Pragma("unroll")                                                           \
        for (int j = 0; j < 4; j++) {                                               \
            const int c = tid + 512 * j;                                            \
            const int row = c >> 3, h = c & 7;                                      \
            cpasync16(sst + STG_B + row * ROWB + h * 16,                            \
                      pBh + (size_t)(n0 + row) * (KP * 2) + k0b + h * 16);          \
        }                                                                           \
        asm volatile("cp.async.commit_group;" ::: "memory");                        \
    }

    LOAD_TILE(0, 0);
    LOAD_TILE(1, 1);

    const int lmat = lane >> 3, lr = lane & 7;       // ldmatrix lane roles
    int stage = 0;
    for (int kt = 0; kt < KT64; kt++) {
        asm volatile("cp.async.wait_group 1;" ::: "memory");   // tile kt resident
        __syncthreads();                                       // + compute(kt-1) done
        if (kt + 2 < KT64) {
            const int ns = (stage + 2 >= NSTAGE) ? stage + 2 - NSTAGE : stage + 2;
            LOAD_TILE(kt + 2, ns);
        } else {
            asm volatile("cp.async.commit_group;" ::: "memory");  // keep group count
        }

        const uint32_t s = sbase + stage * STAGE_SZ;
#pragma unroll
        for (int kk = 0; kk < 4; kk++) {
            const int h = kk * 2 + (lmat >> 1);
            uint32_t ah[2][4], bh[4][4];
#pragma unroll
            for (int mt = 0; mt < 2; mt++) {
                const int row = wm + mt * 16 + (lmat & 1) * 8 + lr;
                ldsm4(ah[mt], s + STG_A + row * ROWB + h * 16);
            }
#pragma unroll
            for (int np = 0; np < 4; np++) {
                const int row = wn + np * 16 + (lmat & 1) * 8 + lr;
                ldsm4(bh[np], s + STG_B + row * ROWB + h * 16);
            }
#pragma unroll
            for (int mt = 0; mt < 2; mt++)
#pragma unroll
                for (int nt = 0; nt < 8; nt++) {
                    const int np = nt >> 1, sub = nt & 1;
                    mma16816(acc[mt][nt], ah[mt], bh[np][sub], bh[np][sub + 2]);
                }
        }
        stage = (stage + 1 >= NSTAGE) ? 0 : stage + 1;
    }

    // epilogue
    if (mat < 7) {
        __half* dsth = xrelh + (size_t)mat * N * 256;
#pragma unroll
        for (int mt = 0; mt < 2; mt++) {
#pragma unroll
            for (int nt = 0; nt < 8; nt++) {
                const int c = wn + nt * 8 + 2 * (lane & 3);
                const int r0 = m0 + wm + mt * 16 + (lane >> 2);
                if (r0 < N)
                    *(__half2*)&dsth[(size_t)r0 * 256 + c] =
                        __floats2half2_rn(acc[mt][nt][0], acc[mt][nt][1]);
                const int r1 = r0 + 8;
                if (r1 < N)
                    *(__half2*)&dsth[(size_t)r1 * 256 + c] =
                        __floats2half2_rn(acc[mt][nt][2], acc[mt][nt][3]);
            }
        }
    } else {
#pragma unroll
        for (int mt = 0; mt < 2; mt++) {
#pragma unroll
            for (int nt = 0; nt < 8; nt++) {
                const int c = wn + nt * 8 + 2 * (lane & 3);
                const float bb0 = b1[c], bb1 = b1[c + 1];
                const int r0 = m0 + wm + mt * 16 + (lane >> 2);
                if (r0 < N)
                    *(float2*)&out1[(size_t)r0 * 256 + c] =
                        make_float2(acc[mt][nt][0] + bb0, acc[mt][nt][1] + bb1);
                const int r1 = r0 + 8;
                if (r1 < N)
                    *(float2*)&out1[(size_t)r1 * 256 + c] =
                        make_float2(acc[mt][nt][2] + bb0, acc[mt][nt][3] + bb1);
            }
        }
    }
}

// ---------------- layer-1 aggregation (atomic-free): warp per dst node, rel window -------
__global__ void __launch_bounds__(256) gather1_kernel(int N, int tlo, int thi) {
    const int d    = (blockIdx.x * 256 + threadIdx.x) >> 5;
    const int lane = threadIdx.x & 31;
    if (d >= N) return;
    const int beg = g_off[d], end = g_off[d + 1];
    float acc[8];
#pragma unroll
    for (int i = 0; i < 8; i++) acc[i] = 0.0f;
    for (int j = beg; j < end; j++) {
        const int p = g_csr[j];
        const int t = p >> 20;
        if (t < tlo || t > thi) continue;
        const int s = p & 0xFFFFF;
        const float w = g_invcnt[(size_t)t * N + d];
        const uint4 v = ((const uint4*)&g_xrelh[((size_t)t * N + s) * D_HID])[lane];
        const __half2* hp = (const __half2*)&v;
        const float2 f0 = __half22float2(hp[0]), f1 = __half22float2(hp[1]);
        const float2 f2 = __half22float2(hp[2]), f3 = __half22float2(hp[3]);
        acc[0] += w * f0.x; acc[1] += w * f0.y; acc[2] += w * f1.x; acc[3] += w * f1.y;
        acc[4] += w * f2.x; acc[5] += w * f2.y; acc[6] += w * f3.x; acc[7] += w * f3.y;
    }
    float* dstp = &g_out1[(size_t)d * D_HID + lane * 8];
    float4 o0 = *(float4*)dstp, o1 = *(float4*)(dstp + 4);
    o0.x += acc[0]; o0.y += acc[1]; o0.z += acc[2]; o0.w += acc[3];
    o1.x += acc[4]; o1.y += acc[5]; o1.z += acc[6]; o1.w += acc[7];
    *(float4*)dstp = o0; *(float4*)(dstp + 4) = o1;
}

// ---------------- fused tail: gather rels [0,1] + relu + layer-2 transforms --------------
__global__ void __launch_bounds__(256) gather_tail_l2_kernel(
    const float* __restrict__ w2rel, const float* __restrict__ w2root,
    const float* __restrict__ b2, float* __restrict__ out, int N)
{
    __shared__ float ws[16][D_HID];
    const int tid = threadIdx.x;
    for (int idx = tid; idx < 16 * D_HID; idx += 256) {
        const int o = idx >> 8, k = idx & 255;
        float v;
        if (o < 14) v = w2rel[((size_t)(o >> 1) * D_HID + k) * 2 + (o & 1)];
        else        v = w2root[(size_t)k * 2 + (o & 1)];
        ws[o][k] = v;
    }
    __syncthreads();

    const int d    = (blockIdx.x * 256 + tid) >> 5;
    const int lane = tid & 31;
    if (d >= N) return;

    float acc[8];
    {
        const float4 o0 = *(const float4*)&g_out1[(size_t)d * D_HID + lane * 8];
        const float4 o1 = *(const float4*)&g_out1[(size_t)d * D_HID + lane * 8 + 4];
        acc[0] = o0.x; acc[1] = o0.y; acc[2] = o0.z; acc[3] = o0.w;
        acc[4] = o1.x; acc[5] = o1.y; acc[6] = o1.z; acc[7] = o1.w;
    }
    const int beg = g_off[d], end = g_off[d + 1];
    for (int j = beg; j < end; j++) {
        const int p = g_csr[j];
        const int t = p >> 20;
        if (t > 1) continue;
        const int s = p & 0xFFFFF;
        const float w = g_invcnt[(size_t)t * N + d];
        const uint4 v = ((const uint4*)&g_xrelh[((size_t)t * N + s) * D_HID])[lane];
        const __half2* hp = (const __half2*)&v;
        const float2 f0 = __half22float2(hp[0]), f1 = __half22float2(hp[1]);
        const float2 f2 = __half22float2(hp[2]), f3 = __half22float2(hp[3]);
        acc[0] += w * f0.x; acc[1] += w * f0.y; acc[2] += w * f1.x; acc[3] += w * f1.y;
        acc[4] += w * f2.x; acc[5] += w * f2.y; acc[6] += w * f3.x; acc[7] += w * f3.y;
    }
#pragma unroll
    for (int i = 0; i < 8; i++) acc[i] = fmaxf(acc[i], 0.0f);

#pragma unroll
    for (int o = 0; o < 16; o++) {
        float sacc = 0.0f;
#pragma unroll
        for (int i = 0; i < 8; i++) sacc += acc[i] * ws[o][lane * 8 + i];
#pragma unroll
        for (int off = 16; off; off >>= 1) sacc += __shfl_xor_sync(0xffffffffu, sacc, off);
        if (lane == 0) {
            if (o < 14) g_h2[((size_t)(o >> 1) * N + d) * 2 + (o & 1)] = sacc;
            else        out[(size_t)d * 2 + (o & 1)] = sacc + b2[o & 1];
        }
    }
}

// ---------------- layer-2 edge scatter (tiny; atomics fine) ----------------
__global__ void scatter2_kernel(float* __restrict__ out, int E, int N) {
    const int e = blockIdx.x * blockDim.x + threadIdx.x;
    if (e >= E) return;
    const int s = g_src[e], d = g_dst[e], t = g_et[e];
    const float w = g_invcnt[(size_t)t * N + d];
    const float2 v = *(const float2*)&g_h2[((size_t)t * N + s) * 2];
    asm volatile("red.global.add.v2.f32 [%0], {%1, %2};"
                 :: "l"(out + (size_t)d * 2), "f"(v.x * w), "f"(v.y * w)
                 : "memory");
}

// ---------------- launch ----------------
extern "C" void kernel_launch(void* const* d_in, const int* in_sizes, int n_in,
                              void* d_out, int out_size) {
    const float* x       = (const float*)d_in[0];
    const void*  ei      = d_in[1];
    const void*  et      = d_in[2];
    const float* w1_rel  = (const float*)d_in[3];
    const float* w1_root = (const float*)d_in[4];
    const float* b1      = (const float*)d_in[5];
    const float* w2_rel  = (const float*)d_in[6];
    const float* w2_root = (const float*)d_in[7];
    const float* b2      = (const float*)d_in[8];
    float* out = (float*)d_out;

    const int N = in_sizes[0] / D_IN;
    const int E = in_sizes[2];

    static __half *Ah_p = nullptr, *Bh_p = nullptr, *xrelh_p = nullptr;
    static float *out1_p = nullptr;
    static cudaStream_t s2 = nullptr, s3 = nullptr;
    static cudaEvent_t evFork = nullptr, evW = nullptr, evX2 = nullptr, evX34 = nullptr,
                       evA = nullptr, evB = nullptr, evDone = nullptr;
    if (!Ah_p) {
        cudaGetSymbolAddress((void**)&Ah_p, g_Ah);
        cudaGetSymbolAddress((void**)&Bh_p, g_Bh);
        cudaGetSymbolAddress((void**)&xrelh_p, g_xrelh);
        cudaGetSymbolAddress((void**)&out1_p, g_out1);
        cudaFuncSetAttribute(hmma_gemm, cudaFuncAttributeMaxDynamicSharedMemorySize, GEMM_SMEM);
        cudaStreamCreateWithFlags(&s2, cudaStreamNonBlocking);
        cudaStreamCreateWithFlags(&s3, cudaStreamNonBlocking);
        cudaEventCreateWithFlags(&evFork, cudaEventDisableTiming);
        cudaEventCreateWithFlags(&evW, cudaEventDisableTiming);
        cudaEventCreateWithFlags(&evX2, cudaEventDisableTiming);
        cudaEventCreateWithFlags(&evX34, cudaEventDisableTiming);
        cudaEventCreateWithFlags(&evA, cudaEventDisableTiming);
        cudaEventCreateWithFlags(&evB, cudaEventDisableTiming);
        cudaEventCreateWithFlags(&evDone, cudaEventDisableTiming);
    }

    const int QT = MTILES / 4;             // 98 row tiles per quarter
    cudaEventRecord(evFork, 0);
    cudaStreamWaitEvent(s2, evFork, 0);
    cudaStreamWaitEvent(s3, evFork, 0);

    // s3: convert X quarters 3+4 (hidden under main's q1 convert + first GEMM)
    convert_x<<<2 * QT * 128, 256, 0, s3>>>(x, Ah_p, N, 2 * QT * 128);
    cudaEventRecord(evX34, s3);

    // s2: weight transpose + X quarter 2, then the CSR chain
    dim3 gw((KP + 255) / 256, NMATS * 256);
    convert_w<<<gw, 256, 0, s2>>>(w1_rel, w1_root, Bh_p);
    cudaEventRecord(evW, s2);
    convert_x<<<QT * 128, 256, 0, s2>>>(x, Ah_p, N, QT * 128);
    cudaEventRecord(evX2, s2);

    detect_kernel<<<1, 128, 0, s2>>>((const unsigned int*)ei, (const unsigned int*)et, E);
    decode_kernel<<<(E + 255) / 256, 256, 0, s2>>>(ei, et, E);
    const int NC = N_RELS * N;
    zero_kernel<<<(NC + 255) / 256, 256, 0, s2>>>(NC, N);
    count_kernel<<<(E + 255) / 256, 256, 0, s2>>>(E, N);
    scan_kernel<<<1, 1024, 0, s2>>>(N);
    invcnt_kernel<<<(NC + 255) / 256, 256, 0, s2>>>(NC);
    fill_kernel<<<(E + 255) / 256, 256, 0, s2>>>(E);

    // main: X quarter 1, then GEMM slices gated on convert events
    convert_x<<<QT * 128, 256>>>(x, Ah_p, N, 0);
    cudaStreamWaitEvent(0, evW, 0);
    dim3 ggQ(6, QT);
    hmma_gemm<<<ggQ, 512, GEMM_SMEM>>>(Ah_p, Bh_p, b1, xrelh_p, out1_p, N, 2, 0);
    cudaStreamWaitEvent(0, evX2, 0);
    hmma_gemm<<<ggQ, 512, GEMM_SMEM>>>(Ah_p, Bh_p, b1, xrelh_p, out1_p, N, 2, QT);
    cudaStreamWaitEvent(0, evX34, 0);
    dim3 ggH(6, MTILES - 2 * QT);
    hmma_gemm<<<ggH, 512, GEMM_SMEM>>>(Ah_p, Bh_p, b1, xrelh_p, out1_p, N, 2, 2 * QT);
    cudaEventRecord(evA, 0);
    dim3 ggB(2, MTILES);
    hmma_gemm<<<ggB, 512, GEMM_SMEM>>>(Ah_p, Bh_p, b1, xrelh_p, out1_p, N, 0, 0);
    cudaEventRecord(evB, 0);

    // s2: gather rels 2..6 under GEMM-B, then fused tail (rels 0..1 + relu + layer2)
    cudaStreamWaitEvent(s2, evA, 0);
    gather1_kernel<<<(N * 32 + 255) / 256, 256, 0, s2>>>(N, 2, 6);
    cudaStreamWaitEvent(s2, evB, 0);
    gather_tail_l2_kernel<<<(N * 32 + 255) / 256, 256, 0, s2>>>(w2_rel, w2_root, b2, out, N);
    scatter2_kernel<<<(E + 255) / 256, 256, 0, s2>>>(out, E, N);

    // join back to the capture stream
    cudaEventRecord(evDone, s2);
    cudaStreamWaitEvent(0, evDone, 0);
}